// round 12
// baseline (speedup 1.0000x reference)
#include <cuda_runtime.h>
#include <cuda_bf16.h>
#include <math.h>
#include <stdint.h>

#define LYRS   2
#define HDIM   512
#define NHEAD  32
#define BATCH  8
#define SEQ    4096
#define MROWS  (BATCH*SEQ)
#define BLH    (MROWS*HDIM)
#define NCHK   4
#define CHLEN  (SEQ/NCHK)            /* 1024 */

// GEMM tiling: CTA 128x128, 8 warps of 64x32, BK=64, 3-stage cp.async
#define BM 128
#define BN 128
#define BK 64
#define STAGE_B 65536
#define SM_ST   1024
#define GEMM_SMEM (SM_ST + 3*STAGE_B)   /* 197632 */
#define LNTR_SMEM (512*33*4)            /* 67584 */

// ---------------- scratch ----------------------------------------------------
__device__ float Fo1[BLH], Ftmp[BLH], FoutB[BLH];
__device__ __nv_bfloat16 P0h[BLH], P0l[BLH], P1h[BLH], P1l[BLH];
__device__ __nv_bfloat16 WTh[10*HDIM*HDIM], WTl[10*HDIM*HDIM];
__device__ float g_lam_re[LYRS*HDIM*NHEAD], g_lam_im[LYRS*HDIM*NHEAD];
__device__ float g_co_re [LYRS*HDIM*NHEAD], g_co_im [LYRS*HDIM*NHEAD];
__device__ float Gfin_re[BATCH*HDIM*NCHK*32], Gfin_im[BATCH*HDIM*NCHK*32];
__device__ float Gcar_re[BATCH*HDIM*NCHK*32], Gcar_im[BATCH*HDIM*NCHK*32];

// ---------------- PTX helpers --------------------------------------------------
__device__ __forceinline__ uint32_t smem_u32(const void* p) {
    uint32_t a;
    asm("{ .reg .u64 t; cvta.to.shared.u64 t, %1; cvt.u32.u64 %0, t; }"
        : "=r"(a) : "l"(p));
    return a;
}
#define CP16(dst, src) \
    asm volatile("cp.async.cg.shared.global [%0], [%1], 16;" \
        :: "r"(dst), "l"(src) : "memory")
#define CP_COMMIT() asm volatile("cp.async.commit_group;" ::: "memory")
#define CP_WAIT(n)  asm volatile("cp.async.wait_group %0;" :: "n"(n) : "memory")

#define LDSM_X4(r0,r1,r2,r3, addr) \
    asm volatile("ldmatrix.sync.aligned.m8n8.x4.shared.b16 {%0,%1,%2,%3}, [%4];" \
        : "=r"(r0),"=r"(r1),"=r"(r2),"=r"(r3) : "r"(addr))

#define MMA16816(d, a0,a1,a2,a3, b0,b1) \
    asm volatile("mma.sync.aligned.m16n8k16.row.col.f32.bf16.bf16.f32 " \
        "{%0,%1,%2,%3}, {%4,%5,%6,%7}, {%8,%9}, {%0,%1,%2,%3};" \
        : "+f"((d)[0]),"+f"((d)[1]),"+f"((d)[2]),"+f"((d)[3]) \
        : "r"(a0),"r"(a1),"r"(a2),"r"(a3), "r"(b0),"r"(b1))

__device__ __forceinline__ uint32_t swz(uint32_t off) { return off ^ ((off >> 3) & 0x70); }
__device__ __forceinline__ float gelu_f(float x) {
    return 0.5f * x * (1.0f + erff(x * 0.70710678118654752440f));
}
__device__ __forceinline__ void split_bf(float v, __nv_bfloat16& h, __nv_bfloat16& l) {
    h = __float2bfloat16(v);
    l = __float2bfloat16(v - __bfloat162float(h));
}

// ---------------- SSM coefficient precompute ----------------------------------
__global__ void prec_k(const float* __restrict__ log_dt,
                       const float* __restrict__ A_re, const float* __restrict__ A_im,
                       const float* __restrict__ B_re, const float* __restrict__ B_im,
                       const float* __restrict__ C_re, const float* __restrict__ C_im)
{
    int idx = blockIdx.x * blockDim.x + threadIdx.x;
    if (idx >= LYRS*HDIM*NHEAD) return;
    int lh = idx / NHEAD;
    float dt = expf(log_dt[lh]);
    float ar = A_re[idx], ai = A_im[idx];
    float e = expf(dt*ar);
    float sn, cs; sincosf(dt*ai, &sn, &cs);
    float lr = e*cs, li = e*sn;
    float nr = lr - 1.0f, ni = li;
    float inv = 1.0f/(ar*ar + ai*ai);
    float dr = (nr*ar + ni*ai)*inv;
    float di = (ni*ar - nr*ai)*inv;
    float br = B_re[idx], bi = B_im[idx];
    float dbr = br*dr - bi*di;
    float dbi = br*di + bi*dr;
    float cr = C_re[idx], ci = C_im[idx];
    g_co_re[idx] = 2.0f*(cr*dbr - ci*dbi);
    g_co_im[idx] = 2.0f*(cr*dbi + ci*dbr);
    g_lam_re[idx] = lr;
    g_lam_im[idx] = li;
}

// ---------------- weight transpose + hi/lo split --------------------------------
__global__ void wconv_k(const float* __restrict__ Wk, const float* __restrict__ W1,
                        const float* __restrict__ Wproj, const float* __restrict__ W2,
                        const float* __restrict__ Wout)
{
    int widx = blockIdx.z;
    int l = widx / 5, t = widx % 5;
    const float* src = (t==0 ? Wk : t==1 ? W1 : t==2 ? Wproj : t==3 ? W2 : Wout)
                       + (size_t)l * HDIM * HDIM;
    __shared__ float tile[32][33];
    int tx = threadIdx.x, ty = threadIdx.y;
    int n0 = blockIdx.x*32, k0 = blockIdx.y*32;
    #pragma unroll
    for (int i = 0; i < 4; ++i)
        tile[ty + 8*i][tx] = src[(size_t)(k0 + ty + 8*i)*HDIM + n0 + tx];
    __syncthreads();
    #pragma unroll
    for (int i = 0; i < 4; ++i) {
        float v = tile[tx][ty + 8*i];
        size_t o = (size_t)widx*HDIM*HDIM + (size_t)(n0 + ty + 8*i)*HDIM + k0 + tx;
        __nv_bfloat16 h, lo; split_bf(v, h, lo);
        WTh[o] = h; WTl[o] = lo;
    }
}

// ---------------- fused LN1 + transpose: [B,L,H] fp32 -> LN -> [B,H,L] fp32 ----
__global__ void __launch_bounds__(256)
ln_tr_k(const float* __restrict__ src, const float* __restrict__ g,
        const float* __restrict__ b, float* __restrict__ dst)
{
    extern __shared__ float tile[];          // [512][33]
    __shared__ float mu_s[32], rs_s[32];
    const int tid = threadIdx.x;
    const int t0  = blockIdx.x * 32;
    const int bb  = blockIdx.y;
    const int wid = tid >> 5, lane = tid & 31;

    const float* sp = src + ((size_t)bb*SEQ + t0)*HDIM;
    const int r = tid >> 3, c8 = tid & 7;
    #pragma unroll
    for (int j = 0; j < 16; ++j) {
        int c4 = c8 + 8*j;
        float4 v = *(const float4*)(sp + (size_t)r*HDIM + c4*4);
        tile[(c4*4+0)*33 + r] = v.x;
        tile[(c4*4+1)*33 + r] = v.y;
        tile[(c4*4+2)*33 + r] = v.z;
        tile[(c4*4+3)*33 + r] = v.w;
    }
    __syncthreads();

    #pragma unroll
    for (int rr = wid*4; rr < wid*4 + 4; ++rr) {
        float s = 0.f, q = 0.f;
        #pragma unroll
        for (int j = 0; j < 16; ++j) {
            float v = tile[(lane + 32*j)*33 + rr];
            s += v; q += v*v;
        }
        #pragma unroll
        for (int o = 16; o; o >>= 1) {
            s += __shfl_xor_sync(0xffffffffu, s, o);
            q += __shfl_xor_sync(0xffffffffu, q, o);
        }
        if (lane == 0) {
            float mu = s * (1.0f/HDIM);
            mu_s[rr] = mu;
            rs_s[rr] = rsqrtf(q*(1.0f/HDIM) - mu*mu + 1e-5f);
        }
    }
    __syncthreads();

    float* dp = dst + (size_t)bb*HDIM*SEQ + t0;
    const int tq = tid & 7;
    #pragma unroll
    for (int j = 0; j < 16; ++j) {
        int h = (tid >> 3) + 32*j;
        float gv = __ldg(g + h), bv = __ldg(b + h);
        float4 o;
        o.x = (tile[h*33 + tq*4+0] - mu_s[tq*4+0])*rs_s[tq*4+0]*gv + bv;
        o.y = (tile[h*33 + tq*4+1] - mu_s[tq*4+1])*rs_s[tq*4+1]*gv + bv;
        o.z = (tile[h*33 + tq*4+2] - mu_s[tq*4+2])*rs_s[tq*4+2]*gv + bv;
        o.w = (tile[h*33 + tq*4+3] - mu_s[tq*4+3])*rs_s[tq*4+3]*gv + bv;
        *(float4*)(dp + (size_t)h*SEQ + tq*4) = o;
    }
}

// ---------------- LayerNorm: fp32 in -> bf16 hi/lo out --------------------------
__global__ void __launch_bounds__(128)
ln_k(const float* __restrict__ src, const float* __restrict__ g,
     const float* __restrict__ b,
     __nv_bfloat16* __restrict__ dsth, __nv_bfloat16* __restrict__ dstl)
{
    const int m = blockIdx.x, tid = threadIdx.x;
    const float4 v = *(const float4*)(src + (size_t)m*HDIM + tid*4);
    float s = v.x + v.y + v.z + v.w;
    float q = v.x*v.x + v.y*v.y + v.z*v.z + v.w*v.w;
    #pragma unroll
    for (int o = 16; o; o >>= 1) {
        s += __shfl_xor_sync(0xffffffffu, s, o);
        q += __shfl_xor_sync(0xffffffffu, q, o);
    }
    __shared__ float ss[4], qq[4], mu_s, rs_s;
    int w = tid >> 5;
    if ((tid & 31) == 0) { ss[w] = s; qq[w] = q; }
    __syncthreads();
    if (tid == 0) {
        float S = ss[0]+ss[1]+ss[2]+ss[3];
        float Q = qq[0]+qq[1]+qq[2]+qq[3];
        float mu = S*(1.0f/HDIM);
        mu_s = mu; rs_s = rsqrtf(Q*(1.0f/HDIM) - mu*mu + 1e-5f);
    }
    __syncthreads();
    const float mu = mu_s, rs = rs_s;
    const float4 gv = *(const float4*)(g + tid*4);
    const float4 bv = *(const float4*)(b + tid*4);
    float4 o;
    o.x = (v.x - mu)*rs*gv.x + bv.x;
    o.y = (v.y - mu)*rs*gv.y + bv.y;
    o.z = (v.z - mu)*rs*gv.z + bv.z;
    o.w = (v.w - mu)*rs*gv.w + bv.w;
    size_t off = (size_t)m*HDIM + tid*4;
    __nv_bfloat16 h0,h1,h2,h3,l0,l1,l2,l3;
    split_bf(o.x,h0,l0); split_bf(o.y,h1,l1);
    split_bf(o.z,h2,l2); split_bf(o.w,h3,l3);
    __nv_bfloat162 a0, a1, c0, c1;
    a0.x=h0; a0.y=h1; a1.x=h2; a1.y=h3;
    c0.x=l0; c0.y=l1; c1.x=l2; c1.y=l3;
    *(uint2*)(dsth + off) = make_uint2(*(uint32_t*)&a0, *(uint32_t*)&a1);
    *(uint2*)(dstl + off) = make_uint2(*(uint32_t*)&c0, *(uint32_t*)&c1);
}

// ---------------- scan pass 1: chunk-local recurrence --------------------------
// warp = (b, h, chunk). Writes partial y (mode-sum + D*z) fp32 [B,H,L] and the
// 32 per-mode final states. No __syncthreads (per-warp smem only).
__global__ void __launch_bounds__(128)
scan1_k(const float* __restrict__ zt, float* __restrict__ part,
        const float* __restrict__ Dvec, int l)
{
    __shared__ float st_s[4][32*36];
    __shared__ float zst[4][32];
    const int tid  = threadIdx.x;
    const int wid  = tid >> 5;
    const int lane = tid & 31;
    const int c    = blockIdx.x & (NCHK-1);
    const int hg   = (blockIdx.x >> 2) & 127;
    const int b    = blockIdx.x >> 9;
    const int h    = hg*4 + wid;
    const int base = l*HDIM*NHEAD + h*NHEAD + lane;
    const float lr = g_lam_re[base], li = g_lam_im[base];
    const float cr = g_co_re[base],  ci = g_co_im[base];
    const float nci = -ci;
    const float dsk = Dvec[h];
    const size_t rowoff = ((size_t)b*HDIM + h)*SEQ + c*CHLEN;
    const float* zp = zt + rowoff;
    float* pp = part + rowoff;
    float* st = st_s[wid];
    float* zs = zst[wid];
    float sr = 0.0f, si = 0.0f;

    float zv = zp[lane];
    for (int t0 = 0; t0 < CHLEN; t0 += 32) {
        float zv_next = (t0 + 32 < CHLEN) ? zp[t0 + 32 + lane] : 0.0f;
        zs[lane] = zv;
        __syncwarp();
        #pragma unroll
        for (int tt = 0; tt < 32; ++tt) {
            float zv_t = zs[tt];
            float tmp  = fmaf(-li, si, zv_t);
            float nsi  = fmaf(li, sr, lr*si);
            sr = fmaf(lr, sr, tmp);
            si = nsi;
            st[tt*36 + lane] = fmaf(cr, sr, nci*si);
        }
        __syncwarp();
        float a0 = 0.f, a1 = 0.f, a2 = 0.f, a3 = 0.f;
        const float4* rp = (const float4*)&st[lane*36];
        #pragma unroll
        for (int i = 0; i < 8; ++i) {
            float4 v4 = rp[i];
            a0 += v4.x; a1 += v4.y; a2 += v4.z; a3 += v4.w;
        }
        pp[t0 + lane] = (a0 + a1) + (a2 + a3) + dsk * zv;
        zv = zv_next;
        __syncwarp();
    }
    const int gidx = (((b*HDIM + h)*NCHK) + c)*32 + lane;
    Gfin_re[gidx] = sr;
    Gfin_im[gidx] = si;
}

// ---------------- combine: carries across chunks -------------------------------
__global__ void __launch_bounds__(256)
comb_k(int l)
{
    int idx = blockIdx.x * blockDim.x + threadIdx.x;   // b*HDIM*32
    if (idx >= BATCH*HDIM*32) return;
    int n = idx & 31, h = (idx >> 5) & (HDIM-1), b = idx >> 14;
    int base = l*HDIM*NHEAD + h*NHEAD + n;
    float a = g_lam_re[base], bb = g_lam_im[base];
    #pragma unroll
    for (int i = 0; i < 10; ++i) {                     // lambda^1024
        float na = a*a - bb*bb;
        bb = 2.0f*a*bb;
        a = na;
    }
    float sr = 0.0f, si = 0.0f;
    int gb = ((b*HDIM + h)*NCHK)*32 + n;
    #pragma unroll
    for (int c = 0; c < NCHK; ++c) {
        Gcar_re[gb + c*32] = sr;
        Gcar_im[gb + c*32] = si;
        float fr = Gfin_re[gb + c*32], fi = Gfin_im[gb + c*32];
        float nr = a*sr - bb*si + fr;
        float ni = a*si + bb*sr + fi;
        sr = nr; si = ni;
    }
}

// ---------------- scan pass 2: correction + gelu + bf16 split -------------------
__global__ void __launch_bounds__(128)
scan2_k(const float* __restrict__ part, __nv_bfloat16* __restrict__ yh,
        __nv_bfloat16* __restrict__ yl, int l)
{
    __shared__ float st_s[4][32*36];
    __shared__ float yt[2][32][5];
    const int tid  = threadIdx.x;
    const int wid  = tid >> 5;
    const int lane = tid & 31;
    const int c    = blockIdx.x & (NCHK-1);
    const int hg   = (blockIdx.x >> 2) & 127;
    const int b    = blockIdx.x >> 9;
    const int h    = hg*4 + wid;
    const int base = l*HDIM*NHEAD + h*NHEAD + lane;
    const float lr = g_lam_re[base], li = g_lam_im[base];
    const float cr = g_co_re[base],  ci = g_co_im[base];
    const size_t rowoff = ((size_t)b*HDIM + h)*SEQ + c*CHLEN;
    const float* pp = part + rowoff;
    float* st = st_s[wid];
    const int ot = tid >> 2, oh = tid & 3;

    const int gidx = (((b*HDIM + h)*NCHK) + c)*32 + lane;
    float sr = Gcar_re[gidx], si = Gcar_im[gidx];
    // e = coef * lambda * carry
    float mr = lr*sr - li*si, mi = lr*si + li*sr;
    float er = cr*mr - ci*mi, ei = cr*mi + ci*mr;

    for (int t0 = 0; t0 < CHLEN; t0 += 32) {
        float pv = pp[t0 + lane];
        #pragma unroll
        for (int tt = 0; tt < 32; ++tt) {
            st[tt*36 + lane] = er;
            float ner = lr*er - li*ei;
            ei = fmaf(lr, ei, li*er);
            er = ner;
        }
        __syncwarp();
        float a0 = 0.f, a1 = 0.f, a2 = 0.f, a3 = 0.f;
        const float4* rp = (const float4*)&st[lane*36];
        #pragma unroll
        for (int i = 0; i < 8; ++i) {
            float4 v4 = rp[i];
            a0 += v4.x; a1 += v4.y; a2 += v4.z; a3 += v4.w;
        }
        const int buf = (t0 >> 5) & 1;
        yt[buf][lane][wid] = gelu_f(pv + (a0 + a1) + (a2 + a3));
        __syncthreads();
        float v = yt[buf][ot][oh];
        __nv_bfloat16 hh, ll; split_bf(v, hh, ll);
        size_t off = ((size_t)(b*SEQ + c*CHLEN + t0 + ot))*HDIM + hg*4 + oh;
        yh[off] = hh; yl[off] = ll;
    }
}

// ---------------- bf16x3 mma.sync GEMM: 3-stage, 1 sync/chunk -------------------
template<int EPI, bool WF32, bool WHL>
__global__ void __launch_bounds__(256, 1)
tgemm_k(const __nv_bfloat16* __restrict__ ah, const __nv_bfloat16* __restrict__ al,
        const __nv_bfloat16* __restrict__ wh, const __nv_bfloat16* __restrict__ wl,
        const float* __restrict__ bias, const float* __restrict__ res,
        float* __restrict__ outf,
        __nv_bfloat16* __restrict__ outh, __nv_bfloat16* __restrict__ outl)
{
    extern __shared__ __align__(1024) char smem[];
    const uint32_t sb = smem_u32(smem);
    const int tid  = threadIdx.x;
    const int wid  = tid >> 5;
    const int lane = tid & 31;
    const int wm   = wid & 1;
    const int wn   = wid >> 1;
    const int n0   = blockIdx.x * BN;
    const int m0   = blockIdx.y * BM;

    if (tid < BN) ((float*)smem)[tid] = bias[n0 + tid];

    const __nv_bfloat16* Ah = ah + (size_t)m0 * HDIM;
    const __nv_bfloat16* Al = al + (size_t)m0 * HDIM;
    const __nv_bfloat16* Wh = wh + (size_t)n0 * HDIM;
    const __nv_bfloat16* Wl = wl + (size_t)n0 * HDIM;

    const int ldr = tid >> 3, ldc = tid & 7;
    auto load_chunk = [&](int ch, int st) {
        const uint32_t so = sb + SM_ST + st*STAGE_B;
        const int cofs = ch * BK;
        #pragma unroll
        for (int t = 0; t < 4; ++t) {
            int r = ldr + t*32;
            uint32_t dst = so + swz(r*128 + ldc*16);
            size_t gsrc = (size_t)r*HDIM + cofs + ldc*8;
            CP16(dst,         Ah + gsrc);
            CP16(dst + 16384, Al + gsrc);
            CP16(dst + 32768, Wh + gsrc);
            CP16(dst + 49152, Wl + gsrc);
        }
        CP_COMMIT();
    };

    float acc[4][4][4];
    #pragma unroll
    for (int i = 0; i < 4; ++i)
        #pragma unroll
        for (int j = 0; j < 4; ++j)
            #pragma unroll
            for (int r = 0; r < 4; ++r) acc[i][j][r] = 0.0f;

    load_chunk(0, 0);
    load_chunk(1, 1);

    const int lr16 = lane & 15, lk = lane >> 4;
    for (int ch = 0; ch < 8; ++ch) {
        if (ch < 7) { CP_WAIT(1); } else { CP_WAIT(0); }
        __syncthreads();
        if (ch + 2 < 8) load_chunk(ch + 2, (ch + 2) % 3);
        const uint32_t so = sb + SM_ST + (ch % 3)*STAGE_B;
        #pragma unroll
        for (int kk = 0; kk < 4; ++kk) {
            const uint32_t ka = kk*32 + lk*16;
            uint32_t fah[4][4], fal[4][4];
            #pragma unroll
            for (int mi = 0; mi < 4; ++mi) {
                uint32_t ad = so + swz((wm*64 + mi*16 + lr16)*128 + ka);
                LDSM_X4(fah[mi][0], fah[mi][1], fah[mi][2], fah[mi][3], ad);
                LDSM_X4(fal[mi][0], fal[mi][1], fal[mi][2], fal[mi][3], ad + 16384);
            }
            uint32_t fbh[2][4], fbl[2][4];
            #pragma unroll
            for (int p = 0; p < 2; ++p) {
                uint32_t bd = so + 32768 + swz((wn*32 + p*16 + lr16)*128 + ka);
                LDSM_X4(fbh[p][0], fbh[p][1], fbh[p][2], fbh[p][3], bd);
                LDSM_X4(fbl[p][0], fbl[p][1], fbl[p][2], fbl[p][3], bd + 16384);
            }
            #pragma unroll
            for (int mi = 0; mi < 4; ++mi) {
                #pragma unroll
                for (int nj = 0; nj < 4; ++nj) {
                    const int p = nj >> 1, j = nj & 1;
                    MMA16816(acc[mi][nj], fah[mi][0], fah[mi][1], fah[mi][2], fah[mi][3],
                             fbh[p][j], fbh[p][j+2]);
                    MMA16816(acc[mi][nj], fah[mi][0], fah[mi][1], fah[mi][2], fah[mi][3],
                             fbl[p][j], fbl[p][j+2]);
                    MMA16816(acc[mi][nj], fal[mi][0], fal[mi][1], fal[mi][2], fal[mi][3],
                             fbh[p][j], fbh[p][j+2]);
                }
            }
        }
    }

    // ---------------- epilogue ----------------
    const float* bsm = (const float*)smem;
    const int rbase = m0 + wm*64;
    const int clb   = wn*32;
    #pragma unroll
    for (int mi = 0; mi < 4; ++mi) {
        #pragma unroll
        for (int nj = 0; nj < 4; ++nj) {
            const int ca = clb + nj*8 + (lane & 3)*2;
            const float b0 = bsm[ca], b1 = bsm[ca + 1];
            #pragma unroll
            for (int hrow = 0; hrow < 2; ++hrow) {
                const int r = rbase + mi*16 + (lane >> 2) + hrow*8;
                float v0 = acc[mi][nj][hrow*2 + 0] + b0;
                float v1 = acc[mi][nj][hrow*2 + 1] + b1;
                const size_t off = (size_t)r * HDIM + n0 + ca;
                if (EPI == 1) {
                    float2 rr = *(const float2*)(res + off);
                    v0 += rr.x; v1 += rr.y;
                }
                if (EPI == 2) { v0 = gelu_f(v0); v1 = gelu_f(v1); }
                if (WF32) *(float2*)(outf + off) = make_float2(v0, v1);
                if (WHL) {
                    __nv_bfloat16 h0, l0, h1, l1;
                    split_bf(v0, h0, l0); split_bf(v1, h1, l1);
                    __nv_bfloat162 hh, ll;
                    hh.x = h0; hh.y = h1; ll.x = l0; ll.y = l1;
                    *(uint32_t*)(outh + off) = *(uint32_t*)&hh;
                    *(uint32_t*)(outl + off) = *(uint32_t*)&ll;
                }
            }
        }
    }
}

// ---------------- orchestration --------------------------------------------------
extern "C" void kernel_launch(void* const* d_in, const int* in_sizes, int n_in,
                              void* d_out, int out_size)
{
    const float* x      = (const float*)d_in[0];
    const float* ln1w   = (const float*)d_in[1];
    const float* ln1b   = (const float*)d_in[2];
    const float* ln2w   = (const float*)d_in[3];
    const float* ln2b   = (const float*)d_in[4];
    const float* log_dt = (const float*)d_in[5];
    const float* A_re   = (const float*)d_in[6];
    const float* A_im   = (const float*)d_in[7];
    const float* B_re   = (const float*)d_in[8];
    const float* B_im   = (const float*)d_in[9];
    const float* C_re   = (const float*)d_in[10];
    const float* C_im   = (const float*)d_in[11];
    const float* Dv     = (const float*)d_in[12];
    const float* Wk     = (const float*)d_in[13];
    const float* bk     = (const float*)d_in[14];
    const float* W1     = (const float*)d_in[15];
    const float* b1     = (const float*)d_in[16];
    const float* W2     = (const float*)d_in[17];
    const float* b2     = (const float*)d_in[18];
    const float* Wout   = (const float*)d_in[19];
    const float* bout   = (const float*)d_in[20];
    const float* Wproj  = (const float*)d_in[21];
    const float* bproj  = (const float*)d_in[22];

    cudaFuncSetAttribute(tgemm_k<0,false,true >, cudaFuncAttributeMaxDynamicSharedMemorySize, GEMM_SMEM);
    cudaFuncSetAttribute(tgemm_k<1,true ,true >, cudaFuncAttributeMaxDynamicSharedMemorySize, GEMM_SMEM);
    cudaFuncSetAttribute(tgemm_k<0,true ,false>, cudaFuncAttributeMaxDynamicSharedMemorySize, GEMM_SMEM);
    cudaFuncSetAttribute(tgemm_k<2,false,true >, cudaFuncAttributeMaxDynamicSharedMemorySize, GEMM_SMEM);
    cudaFuncSetAttribute(tgemm_k<1,true ,false>, cudaFuncAttributeMaxDynamicSharedMemorySize, GEMM_SMEM);
    cudaFuncSetAttribute(ln_tr_k, cudaFuncAttributeMaxDynamicSharedMemorySize, LNTR_SMEM);

    float *fo1, *ftmp, *foutb;
    __nv_bfloat16 *p0h, *p0l, *p1h, *p1l, *wth, *wtl;
    cudaGetSymbolAddress((void**)&fo1,  Fo1);
    cudaGetSymbolAddress((void**)&ftmp, Ftmp);
    cudaGetSymbolAddress((void**)&foutb,FoutB);
    cudaGetSymbolAddress((void**)&p0h,  P0h);
    cudaGetSymbolAddress((void**)&p0l,  P0l);
    cudaGetSymbolAddress((void**)&p1h,  P1h);
    cudaGetSymbolAddress((void**)&p1l,  P1l);
    cudaGetSymbolAddress((void**)&wth,  WTh);
    cudaGetSymbolAddress((void**)&wtl,  WTl);

    prec_k<<<(LYRS*HDIM*NHEAD + 255)/256, 256>>>(log_dt, A_re, A_im, B_re, B_im, C_re, C_im);
    wconv_k<<<dim3(16,16,10), dim3(32,8)>>>(Wk, W1, Wproj, W2, Wout);

    const dim3 gg(HDIM/BN, MROWS/BM);       // (4, 256)
    const size_t WB = (size_t)HDIM*HDIM;
    const float* prev = x;
    for (int l = 0; l < LYRS; ++l) {
        int vo = l * HDIM;
        const __nv_bfloat16 *wkh = wth + (l*5+0)*WB, *wkl = wtl + (l*5+0)*WB;
        const __nv_bfloat16 *w1h = wth + (l*5+1)*WB, *w1l = wtl + (l*5+1)*WB;
        const __nv_bfloat16 *wph = wth + (l*5+2)*WB, *wpl = wtl + (l*5+2)*WB;
        const __nv_bfloat16 *w2h = wth + (l*5+3)*WB, *w2l = wtl + (l*5+3)*WB;
        const __nv_bfloat16 *woh = wth + (l*5+4)*WB, *wol = wtl + (l*5+4)*WB;

        // zT = LN1(prev) transposed -> [B,H,L] fp32 (fused)
        ln_tr_k<<<dim3(SEQ/32, BATCH), 256, LNTR_SMEM>>>(prev, ln1w + vo, ln1b + vo, ftmp);
        // chunked scan: pass1 (local) -> comb (carries) -> pass2 (finalize)
        scan1_k<<<BATCH*128*NCHK, 128>>>(ftmp, fo1, Dv + vo, l);
        comb_k<<<(BATCH*HDIM*32 + 255)/256, 256>>>(l);
        scan2_k<<<BATCH*128*NCHK, 128>>>(fo1, p0h, p0l, l);
        tgemm_k<0,false,true ><<<gg, 256, GEMM_SMEM>>>(p0h, p0l, wkh, wkl,
            bk + vo, nullptr, nullptr, p1h, p1l);
        tgemm_k<1,true ,true ><<<gg, 256, GEMM_SMEM>>>(p1h, p1l, w1h, w1l,
            b1 + vo, prev, fo1, p0h, p0l);
        ln_k<<<MROWS, 128>>>(fo1, ln2w + vo, ln2b + vo, p1h, p1l);
        tgemm_k<0,true ,false><<<gg, 256, GEMM_SMEM>>>(p0h, p0l, wph, wpl,
            bproj + vo, nullptr, ftmp, nullptr, nullptr);
        tgemm_k<2,false,true ><<<gg, 256, GEMM_SMEM>>>(p1h, p1l, w2h, w2l,
            b2 + vo, nullptr, nullptr, p0h, p0l);
        float* op = (l == LYRS-1) ? (float*)d_out : foutb;
        tgemm_k<1,true ,false><<<gg, 256, GEMM_SMEM>>>(p0h, p0l, woh, wol,
            bout + vo, ftmp, op, nullptr, nullptr);
        prev = foutb;
    }
}

// round 13
// speedup vs baseline: 1.2027x; 1.2027x over previous
#include <cuda_runtime.h>
#include <cuda_bf16.h>
#include <math.h>
#include <stdint.h>

#define LYRS   2
#define HDIM   512
#define NHEAD  32
#define BATCH  8
#define SEQ    4096
#define MROWS  (BATCH*SEQ)
#define BLH    (MROWS*HDIM)

// GEMM tiling: CTA 128x128, 8 warps of 64x32, BK=64, 3-stage cp.async
#define BM 128
#define BN 128
#define BK 64
#define STAGE_B 65536
#define SM_ST   1024
#define GEMM_SMEM (SM_ST + 3*STAGE_B)   /* 197632 */
#define LNTR_SMEM (512*33*4)            /* 67584 */

// ---------------- scratch ----------------------------------------------------
__device__ float Fo1[BLH], Ftmp[BLH], FoutB[BLH];
__device__ __nv_bfloat16 P0h[BLH], P0l[BLH], P1h[BLH], P1l[BLH];
__device__ __nv_bfloat16 WTh[10*HDIM*HDIM], WTl[10*HDIM*HDIM];
__device__ __nv_bfloat16 Gwh[LYRS*HDIM*HDIM], Gwl[LYRS*HDIM*HDIM];
__device__ float Bk1[LYRS*HDIM];
__device__ float Zb[HDIM];                 // zero bias (device globals zero-init)
__device__ float g_lam_re[LYRS*HDIM*NHEAD], g_lam_im[LYRS*HDIM*NHEAD];
__device__ float g_co_re [LYRS*HDIM*NHEAD], g_co_im [LYRS*HDIM*NHEAD];

// ---------------- PTX helpers --------------------------------------------------
__device__ __forceinline__ uint32_t smem_u32(const void* p) {
    uint32_t a;
    asm("{ .reg .u64 t; cvta.to.shared.u64 t, %1; cvt.u32.u64 %0, t; }"
        : "=r"(a) : "l"(p));
    return a;
}
#define CP16(dst, src) \
    asm volatile("cp.async.cg.shared.global [%0], [%1], 16;" \
        :: "r"(dst), "l"(src) : "memory")
#define CP_COMMIT() asm volatile("cp.async.commit_group;" ::: "memory")
#define CP_WAIT(n)  asm volatile("cp.async.wait_group %0;" :: "n"(n) : "memory")

#define LDSM_X4(r0,r1,r2,r3, addr) \
    asm volatile("ldmatrix.sync.aligned.m8n8.x4.shared.b16 {%0,%1,%2,%3}, [%4];" \
        : "=r"(r0),"=r"(r1),"=r"(r2),"=r"(r3) : "r"(addr))

#define MMA16816(d, a0,a1,a2,a3, b0,b1) \
    asm volatile("mma.sync.aligned.m16n8k16.row.col.f32.bf16.bf16.f32 " \
        "{%0,%1,%2,%3}, {%4,%5,%6,%7}, {%8,%9}, {%0,%1,%2,%3};" \
        : "+f"((d)[0]),"+f"((d)[1]),"+f"((d)[2]),"+f"((d)[3]) \
        : "r"(a0),"r"(a1),"r"(a2),"r"(a3), "r"(b0),"r"(b1))

__device__ __forceinline__ uint32_t swz(uint32_t off) { return off ^ ((off >> 3) & 0x70); }
__device__ __forceinline__ float gelu_f(float x) {
    return 0.5f * x * (1.0f + erff(x * 0.70710678118654752440f));
}
__device__ __forceinline__ void split_bf(float v, __nv_bfloat16& h, __nv_bfloat16& l) {
    h = __float2bfloat16(v);
    l = __float2bfloat16(v - __bfloat162float(h));
}

// ---------------- SSM coefficient precompute ----------------------------------
__global__ void prec_k(const float* __restrict__ log_dt,
                       const float* __restrict__ A_re, const float* __restrict__ A_im,
                       const float* __restrict__ B_re, const float* __restrict__ B_im,
                       const float* __restrict__ C_re, const float* __restrict__ C_im)
{
    int idx = blockIdx.x * blockDim.x + threadIdx.x;
    if (idx >= LYRS*HDIM*NHEAD) return;
    int lh = idx / NHEAD;
    float dt = expf(log_dt[lh]);
    float ar = A_re[idx], ai = A_im[idx];
    float e = expf(dt*ar);
    float sn, cs; sincosf(dt*ai, &sn, &cs);
    float lr = e*cs, li = e*sn;
    float nr = lr - 1.0f, ni = li;
    float inv = 1.0f/(ar*ar + ai*ai);
    float dr = (nr*ar + ni*ai)*inv;
    float di = (ni*ar - nr*ai)*inv;
    float br = B_re[idx], bi = B_im[idx];
    float dbr = br*dr - bi*di;
    float dbi = br*di + bi*dr;
    float cr = C_re[idx], ci = C_im[idx];
    g_co_re[idx] = 2.0f*(cr*dbr - ci*dbi);
    g_co_im[idx] = 2.0f*(cr*dbi + ci*dbr);
    g_lam_re[idx] = lr;
    g_lam_im[idx] = li;
}

// ---------------- weight transpose + hi/lo split --------------------------------
__global__ void wconv_k(const float* __restrict__ Wk, const float* __restrict__ W1,
                        const float* __restrict__ Wproj, const float* __restrict__ W2,
                        const float* __restrict__ Wout)
{
    int widx = blockIdx.z;
    int l = widx / 5, t = widx % 5;
    const float* src = (t==0 ? Wk : t==1 ? W1 : t==2 ? Wproj : t==3 ? W2 : Wout)
                       + (size_t)l * HDIM * HDIM;
    __shared__ float tile[32][33];
    int tx = threadIdx.x, ty = threadIdx.y;
    int n0 = blockIdx.x*32, k0 = blockIdx.y*32;
    #pragma unroll
    for (int i = 0; i < 4; ++i)
        tile[ty + 8*i][tx] = src[(size_t)(k0 + ty + 8*i)*HDIM + n0 + tx];
    __syncthreads();
    #pragma unroll
    for (int i = 0; i < 4; ++i) {
        float v = tile[tx][ty + 8*i];
        size_t o = (size_t)widx*HDIM*HDIM + (size_t)(n0 + ty + 8*i)*HDIM + k0 + tx;
        __nv_bfloat16 h, lo; split_bf(v, h, lo);
        WTh[o] = h; WTl[o] = lo;
    }
}

// ---------------- elementwise split of Wk (row-major, both layers) -------------
__global__ void esplit_k(const float* __restrict__ Wk)
{
    int idx = blockIdx.x * blockDim.x + threadIdx.x;
    if (idx >= LYRS*HDIM*HDIM) return;
    __nv_bfloat16 h, lo; split_bf(Wk[idx], h, lo);
    Gwh[idx] = h; Gwl[idx] = lo;
}

// ---------------- fused bias: Bk1 = bk @ W1 + b1 --------------------------------
__global__ void bfuse_k(const float* __restrict__ bk, const float* __restrict__ b1,
                        const float* __restrict__ W1)
{
    int l = blockIdx.x, n = threadIdx.x;
    const float* w = W1 + (size_t)l*HDIM*HDIM;
    const float* bb = bk + l*HDIM;
    float s = b1[l*HDIM + n];
    for (int j = 0; j < HDIM; ++j) s = fmaf(bb[j], w[(size_t)j*HDIM + n], s);
    Bk1[l*HDIM + n] = s;
}

// ---------------- fused LN1 + transpose: [B,L,H] fp32 -> LN -> [B,H,L] fp32 ----
__global__ void __launch_bounds__(256)
ln_tr_k(const float* __restrict__ src, const float* __restrict__ g,
        const float* __restrict__ b, float* __restrict__ dst)
{
    extern __shared__ float tile[];          // [512][33]
    __shared__ float mu_s[32], rs_s[32];
    const int tid = threadIdx.x;
    const int t0  = blockIdx.x * 32;
    const int bb  = blockIdx.y;
    const int wid = tid >> 5, lane = tid & 31;

    const float* sp = src + ((size_t)bb*SEQ + t0)*HDIM;
    const int r = tid >> 3, c8 = tid & 7;
    #pragma unroll
    for (int j = 0; j < 16; ++j) {
        int c4 = c8 + 8*j;
        float4 v = *(const float4*)(sp + (size_t)r*HDIM + c4*4);
        tile[(c4*4+0)*33 + r] = v.x;
        tile[(c4*4+1)*33 + r] = v.y;
        tile[(c4*4+2)*33 + r] = v.z;
        tile[(c4*4+3)*33 + r] = v.w;
    }
    __syncthreads();

    #pragma unroll
    for (int rr = wid*4; rr < wid*4 + 4; ++rr) {
        float s = 0.f, q = 0.f;
        #pragma unroll
        for (int j = 0; j < 16; ++j) {
            float v = tile[(lane + 32*j)*33 + rr];
            s += v; q += v*v;
        }
        #pragma unroll
        for (int o = 16; o; o >>= 1) {
            s += __shfl_xor_sync(0xffffffffu, s, o);
            q += __shfl_xor_sync(0xffffffffu, q, o);
        }
        if (lane == 0) {
            float mu = s * (1.0f/HDIM);
            mu_s[rr] = mu;
            rs_s[rr] = rsqrtf(q*(1.0f/HDIM) - mu*mu + 1e-5f);
        }
    }
    __syncthreads();

    float* dp = dst + (size_t)bb*HDIM*SEQ + t0;
    const int tq = tid & 7;
    #pragma unroll
    for (int j = 0; j < 16; ++j) {
        int h = (tid >> 3) + 32*j;
        float gv = __ldg(g + h), bv = __ldg(b + h);
        float4 o;
        o.x = (tile[h*33 + tq*4+0] - mu_s[tq*4+0])*rs_s[tq*4+0]*gv + bv;
        o.y = (tile[h*33 + tq*4+1] - mu_s[tq*4+1])*rs_s[tq*4+1]*gv + bv;
        o.z = (tile[h*33 + tq*4+2] - mu_s[tq*4+2])*rs_s[tq*4+2]*gv + bv;
        o.w = (tile[h*33 + tq*4+3] - mu_s[tq*4+3])*rs_s[tq*4+3]*gv + bv;
        *(float4*)(dp + (size_t)h*SEQ + tq*4) = o;
    }
}

// ---------------- LayerNorm: fp32 in -> bf16 hi/lo out --------------------------
__global__ void __launch_bounds__(128)
ln_k(const float* __restrict__ src, const float* __restrict__ g,
     const float* __restrict__ b,
     __nv_bfloat16* __restrict__ dsth, __nv_bfloat16* __restrict__ dstl)
{
    const int m = blockIdx.x, tid = threadIdx.x;
    const float4 v = *(const float4*)(src + (size_t)m*HDIM + tid*4);
    float s = v.x + v.y + v.z + v.w;
    float q = v.x*v.x + v.y*v.y + v.z*v.z + v.w*v.w;
    #pragma unroll
    for (int o = 16; o; o >>= 1) {
        s += __shfl_xor_sync(0xffffffffu, s, o);
        q += __shfl_xor_sync(0xffffffffu, q, o);
    }
    __shared__ float ss[4], qq[4], mu_s, rs_s;
    int w = tid >> 5;
    if ((tid & 31) == 0) { ss[w] = s; qq[w] = q; }
    __syncthreads();
    if (tid == 0) {
        float S = ss[0]+ss[1]+ss[2]+ss[3];
        float Q = qq[0]+qq[1]+qq[2]+qq[3];
        float mu = S*(1.0f/HDIM);
        mu_s = mu; rs_s = rsqrtf(Q*(1.0f/HDIM) - mu*mu + 1e-5f);
    }
    __syncthreads();
    const float mu = mu_s, rs = rs_s;
    const float4 gv = *(const float4*)(g + tid*4);
    const float4 bv = *(const float4*)(b + tid*4);
    float4 o;
    o.x = (v.x - mu)*rs*gv.x + bv.x;
    o.y = (v.y - mu)*rs*gv.y + bv.y;
    o.z = (v.z - mu)*rs*gv.z + bv.z;
    o.w = (v.w - mu)*rs*gv.w + bv.w;
    size_t off = (size_t)m*HDIM + tid*4;
    __nv_bfloat16 h0,h1,h2,h3,l0,l1,l2,l3;
    split_bf(o.x,h0,l0); split_bf(o.y,h1,l1);
    split_bf(o.z,h2,l2); split_bf(o.w,h3,l3);
    __nv_bfloat162 a0, a1, c0, c1;
    a0.x=h0; a0.y=h1; a1.x=h2; a1.y=h3;
    c0.x=l0; c0.y=l1; c1.x=l2; c1.y=l3;
    *(uint2*)(dsth + off) = make_uint2(*(uint32_t*)&a0, *(uint32_t*)&a1);
    *(uint2*)(dstl + off) = make_uint2(*(uint32_t*)&c0, *(uint32_t*)&c1);
}

// ---------------- S4 scan + D-skip + GELU (R11 proven version) ------------------
__global__ void __launch_bounds__(128)
scan_k(const float* __restrict__ zt, __nv_bfloat16* __restrict__ yh,
       __nv_bfloat16* __restrict__ yl, const float* __restrict__ Dvec, int l)
{
    __shared__ float st_s[4][32*36];
    __shared__ float zst[4][32];
    __shared__ float yt[2][32][9];
    const int tid  = threadIdx.x;
    const int wid  = tid >> 5;
    const int lane = tid & 31;
    const int b    = blockIdx.x >> 7;
    const int hg   = blockIdx.x & 127;
    const int h    = hg*4 + wid;
    const int base = l*HDIM*NHEAD + h*NHEAD + lane;
    const float lr = g_lam_re[base], li = g_lam_im[base];
    const float cr = g_co_re[base],  ci = g_co_im[base];
    const float nci = -ci;
    const float dsk = Dvec[h];
    const float* zp = zt + ((size_t)b*HDIM + h)*SEQ;
    float* st = st_s[wid];
    float* zs = zst[wid];
    const int ot = tid >> 2, oh = tid & 3;
    float sr = 0.0f, si = 0.0f;

    float zv = zp[lane];
    for (int t0 = 0; t0 < SEQ; t0 += 32) {
        float zv_next = (t0 + 32 < SEQ) ? zp[t0 + 32 + lane] : 0.0f;
        zs[lane] = zv;
        __syncwarp();
        #pragma unroll
        for (int tt = 0; tt < 32; ++tt) {
            float zv_t = zs[tt];
            float tmp  = fmaf(-li, si, zv_t);
            float nsi  = fmaf(li, sr, lr*si);
            sr = fmaf(lr, sr, tmp);
            si = nsi;
            st[tt*36 + lane] = fmaf(cr, sr, nci*si);
        }
        __syncwarp();
        float a0 = 0.f, a1 = 0.f, a2 = 0.f, a3 = 0.f;
        const float4* rp = (const float4*)&st[lane*36];
        #pragma unroll
        for (int i = 0; i < 8; ++i) {
            float4 v4 = rp[i];
            a0 += v4.x; a1 += v4.y; a2 += v4.z; a3 += v4.w;
        }
        const int buf = (t0 >> 5) & 1;
        yt[buf][lane][wid] = gelu_f((a0 + a1) + (a2 + a3) + dsk * zv);
        __syncthreads();
        float v = yt[buf][ot][oh];
        __nv_bfloat16 hh, ll; split_bf(v, hh, ll);
        size_t off = ((size_t)(b*SEQ + t0 + ot))*HDIM + hg*4 + oh;
        yh[off] = hh; yl[off] = ll;
        zv = zv_next;
    }
}

// ---------------- bf16x3 mma.sync GEMM: 3-stage, 1 sync/chunk -------------------
template<int EPI, bool WF32, bool WHL>
__global__ void __launch_bounds__(256, 1)
tgemm_k(const __nv_bfloat16* __restrict__ ah, const __nv_bfloat16* __restrict__ al,
        const __nv_bfloat16* __restrict__ wh, const __nv_bfloat16* __restrict__ wl,
        const float* __restrict__ bias, const float* __restrict__ res,
        float* __restrict__ outf,
        __nv_bfloat16* __restrict__ outh, __nv_bfloat16* __restrict__ outl)
{
    extern __shared__ __align__(1024) char smem[];
    const uint32_t sb = smem_u32(smem);
    const int tid  = threadIdx.x;
    const int wid  = tid >> 5;
    const int lane = tid & 31;
    const int wm   = wid & 1;
    const int wn   = wid >> 1;
    const int n0   = blockIdx.x * BN;
    const int m0   = blockIdx.y * BM;

    if (tid < BN) ((float*)smem)[tid] = bias[n0 + tid];

    const __nv_bfloat16* Ah = ah + (size_t)m0 * HDIM;
    const __nv_bfloat16* Al = al + (size_t)m0 * HDIM;
    const __nv_bfloat16* Wh = wh + (size_t)n0 * HDIM;
    const __nv_bfloat16* Wl = wl + (size_t)n0 * HDIM;

    const int ldr = tid >> 3, ldc = tid & 7;
    auto load_chunk = [&](int ch, int st) {
        const uint32_t so = sb + SM_ST + st*STAGE_B;
        const int cofs = ch * BK;
        #pragma unroll
        for (int t = 0; t < 4; ++t) {
            int r = ldr + t*32;
            uint32_t dst = so + swz(r*128 + ldc*16);
            size_t gsrc = (size_t)r*HDIM + cofs + ldc*8;
            CP16(dst,         Ah + gsrc);
            CP16(dst + 16384, Al + gsrc);
            CP16(dst + 32768, Wh + gsrc);
            CP16(dst + 49152, Wl + gsrc);
        }
        CP_COMMIT();
    };

    float acc[4][4][4];
    #pragma unroll
    for (int i = 0; i < 4; ++i)
        #pragma unroll
        for (int j = 0; j < 4; ++j)
            #pragma unroll
            for (int r = 0; r < 4; ++r) acc[i][j][r] = 0.0f;

    load_chunk(0, 0);
    load_chunk(1, 1);

    const int lr16 = lane & 15, lk = lane >> 4;
    for (int ch = 0; ch < 8; ++ch) {
        if (ch < 7) { CP_WAIT(1); } else { CP_WAIT(0); }
        __syncthreads();
        if (ch + 2 < 8) load_chunk(ch + 2, (ch + 2) % 3);
        const uint32_t so = sb + SM_ST + (ch % 3)*STAGE_B;
        #pragma unroll
        for (int kk = 0; kk < 4; ++kk) {
            const uint32_t ka = kk*32 + lk*16;
            uint32_t fah[4][4], fal[4][4];
            #pragma unroll
            for (int mi = 0; mi < 4; ++mi) {
                uint32_t ad = so + swz((wm*64 + mi*16 + lr16)*128 + ka);
                LDSM_X4(fah[mi][0], fah[mi][1], fah[mi][2], fah[mi][3], ad);
                LDSM_X4(fal[mi][0], fal[mi][1], fal[mi][2], fal[mi][3], ad + 16384);
            }
            uint32_t fbh[2][4], fbl[2][4];
            #pragma unroll
            for (int p = 0; p < 2; ++p) {
                uint32_t bd = so + 32768 + swz((wn*32 + p*16 + lr16)*128 + ka);
                LDSM_X4(fbh[p][0], fbh[p][1], fbh[p][2], fbh[p][3], bd);
                LDSM_X4(fbl[p][0], fbl[p][1], fbl[p][2], fbl[p][3], bd + 16384);
            }
            #pragma unroll
            for (int mi = 0; mi < 4; ++mi) {
                #pragma unroll
                for (int nj = 0; nj < 4; ++nj) {
                    const int p = nj >> 1, j = nj & 1;
                    MMA16816(acc[mi][nj], fah[mi][0], fah[mi][1], fah[mi][2], fah[mi][3],
                             fbh[p][j], fbh[p][j+2]);
                    MMA16816(acc[mi][nj], fah[mi][0], fah[mi][1], fah[mi][2], fah[mi][3],
                             fbl[p][j], fbl[p][j+2]);
                    MMA16816(acc[mi][nj], fal[mi][0], fal[mi][1], fal[mi][2], fal[mi][3],
                             fbh[p][j], fbh[p][j+2]);
                }
            }
        }
    }

    // ---------------- epilogue ----------------
    const float* bsm = (const float*)smem;
    const int rbase = m0 + wm*64;
    const int clb   = wn*32;
    #pragma unroll
    for (int mi = 0; mi < 4; ++mi) {
        #pragma unroll
        for (int nj = 0; nj < 4; ++nj) {
            const int ca = clb + nj*8 + (lane & 3)*2;
            const float b0 = bsm[ca], b1 = bsm[ca + 1];
            #pragma unroll
            for (int hrow = 0; hrow < 2; ++hrow) {
                const int r = rbase + mi*16 + (lane >> 2) + hrow*8;
                float v0 = acc[mi][nj][hrow*2 + 0] + b0;
                float v1 = acc[mi][nj][hrow*2 + 1] + b1;
                const size_t off = (size_t)r * HDIM + n0 + ca;
                if (EPI == 1) {
                    float2 rr = *(const float2*)(res + off);
                    v0 += rr.x; v1 += rr.y;
                }
                if (EPI == 2) { v0 = gelu_f(v0); v1 = gelu_f(v1); }
                if (WF32) *(float2*)(outf + off) = make_float2(v0, v1);
                if (WHL) {
                    __nv_bfloat16 h0, l0, h1, l1;
                    split_bf(v0, h0, l0); split_bf(v1, h1, l1);
                    __nv_bfloat162 hh, ll;
                    hh.x = h0; hh.y = h1; ll.x = l0; ll.y = l1;
                    *(uint32_t*)(outh + off) = *(uint32_t*)&hh;
                    *(uint32_t*)(outl + off) = *(uint32_t*)&ll;
                }
            }
        }
    }
}

// ---------------- orchestration --------------------------------------------------
extern "C" void kernel_launch(void* const* d_in, const int* in_sizes, int n_in,
                              void* d_out, int out_size)
{
    const float* x      = (const float*)d_in[0];
    const float* ln1w   = (const float*)d_in[1];
    const float* ln1b   = (const float*)d_in[2];
    const float* ln2w   = (const float*)d_in[3];
    const float* ln2b   = (const float*)d_in[4];
    const float* log_dt = (const float*)d_in[5];
    const float* A_re   = (const float*)d_in[6];
    const float* A_im   = (const float*)d_in[7];
    const float* B_re   = (const float*)d_in[8];
    const float* B_im   = (const float*)d_in[9];
    const float* C_re   = (const float*)d_in[10];
    const float* C_im   = (const float*)d_in[11];
    const float* Dv     = (const float*)d_in[12];
    const float* Wk     = (const float*)d_in[13];
    const float* bk     = (const float*)d_in[14];
    const float* W1     = (const float*)d_in[15];
    const float* b1     = (const float*)d_in[16];
    const float* W2     = (const float*)d_in[17];
    const float* b2     = (const float*)d_in[18];
    const float* Wout   = (const float*)d_in[19];
    const float* bout   = (const float*)d_in[20];
    const float* Wproj  = (const float*)d_in[21];
    const float* bproj  = (const float*)d_in[22];

    cudaFuncSetAttribute(tgemm_k<0,false,true >, cudaFuncAttributeMaxDynamicSharedMemorySize, GEMM_SMEM);
    cudaFuncSetAttribute(tgemm_k<1,true ,true >, cudaFuncAttributeMaxDynamicSharedMemorySize, GEMM_SMEM);
    cudaFuncSetAttribute(tgemm_k<0,true ,false>, cudaFuncAttributeMaxDynamicSharedMemorySize, GEMM_SMEM);
    cudaFuncSetAttribute(tgemm_k<2,false,true >, cudaFuncAttributeMaxDynamicSharedMemorySize, GEMM_SMEM);
    cudaFuncSetAttribute(tgemm_k<1,true ,false>, cudaFuncAttributeMaxDynamicSharedMemorySize, GEMM_SMEM);
    cudaFuncSetAttribute(ln_tr_k, cudaFuncAttributeMaxDynamicSharedMemorySize, LNTR_SMEM);

    float *fo1, *ftmp, *foutb, *zb, *bk1;
    __nv_bfloat16 *p0h, *p0l, *p1h, *p1l, *wth, *wtl, *gwh, *gwl;
    cudaGetSymbolAddress((void**)&fo1,  Fo1);
    cudaGetSymbolAddress((void**)&ftmp, Ftmp);
    cudaGetSymbolAddress((void**)&foutb,FoutB);
    cudaGetSymbolAddress((void**)&p0h,  P0h);
    cudaGetSymbolAddress((void**)&p0l,  P0l);
    cudaGetSymbolAddress((void**)&p1h,  P1h);
    cudaGetSymbolAddress((void**)&p1l,  P1l);
    cudaGetSymbolAddress((void**)&wth,  WTh);
    cudaGetSymbolAddress((void**)&wtl,  WTl);
    cudaGetSymbolAddress((void**)&gwh,  Gwh);
    cudaGetSymbolAddress((void**)&gwl,  Gwl);
    cudaGetSymbolAddress((void**)&zb,   Zb);
    cudaGetSymbolAddress((void**)&bk1,  Bk1);

    prec_k<<<(LYRS*HDIM*NHEAD + 255)/256, 256>>>(log_dt, A_re, A_im, B_re, B_im, C_re, C_im);
    wconv_k<<<dim3(16,16,10), dim3(32,8)>>>(Wk, W1, Wproj, W2, Wout);
    esplit_k<<<(LYRS*HDIM*HDIM + 255)/256, 256>>>(Wk);
    bfuse_k<<<LYRS, HDIM>>>(bk, b1, W1);

    const size_t WB = (size_t)HDIM*HDIM;
    // Wk1^T[n][k] = sum_j W1^T[n][j] * Wk[k][j]  -> overwrite slot (l*5+0)
    for (int l = 0; l < LYRS; ++l) {
        tgemm_k<0,false,true><<<dim3(4,4), 256, GEMM_SMEM>>>(
            wth + (l*5+1)*WB, wtl + (l*5+1)*WB,       // A = W1^T hi/lo
            gwh + l*WB,       gwl + l*WB,             // W = Wk elementwise split
            zb, nullptr, nullptr,
            wth + (l*5+0)*WB, wtl + (l*5+0)*WB);
    }

    const dim3 gg(HDIM/BN, MROWS/BM);       // (4, 256)
    const float* prev = x;
    for (int l = 0; l < LYRS; ++l) {
        int vo = l * HDIM;
        const __nv_bfloat16 *wfh = wth + (l*5+0)*WB, *wfl = wtl + (l*5+0)*WB;  // fused Wk@W1
        const __nv_bfloat16 *wph = wth + (l*5+2)*WB, *wpl = wtl + (l*5+2)*WB;
        const __nv_bfloat16 *w2h = wth + (l*5+3)*WB, *w2l = wtl + (l*5+3)*WB;
        const __nv_bfloat16 *woh = wth + (l*5+4)*WB, *wol = wtl + (l*5+4)*WB;

        // zT = LN1(prev) transposed -> [B,H,L] fp32 (fused)
        ln_tr_k<<<dim3(SEQ/32, BATCH), 256, LNTR_SMEM>>>(prev, ln1w + vo, ln1b + vo, ftmp);
        // y = gelu(ssm(zT) + z*D) -> P0 hi/lo [B,L,H]
        scan_k<<<1024, 128>>>(ftmp, p0h, p0l, Dv + vo, l);
        // o1 = y @ (Wk@W1) + Bk1 + prev -> Fo1 fp32 + P1 hi/lo
        tgemm_k<1,true ,true ><<<gg, 256, GEMM_SMEM>>>(p0h, p0l, wfh, wfl,
            bk1 + vo, prev, fo1, p1h, p1l);
        // z2 = LN2(o1) -> P0 hi/lo
        ln_k<<<MROWS, 128>>>(fo1, ln2w + vo, ln2b + vo, p0h, p0l);
        // tmp = o1 @ Wproj + bproj -> Ftmp fp32
        tgemm_k<0,true ,false><<<gg, 256, GEMM_SMEM>>>(p1h, p1l, wph, wpl,
            bproj + vo, nullptr, ftmp, nullptr, nullptr);
        // h = gelu(z2 @ W2 + b2) -> P1 hi/lo
        tgemm_k<2,false,true ><<<gg, 256, GEMM_SMEM>>>(p0h, p0l, w2h, w2l,
            b2 + vo, nullptr, nullptr, p1h, p1l);
        // out = h @ Wout + bout + tmp -> fp32
        float* op = (l == LYRS-1) ? (float*)d_out : foutb;
        tgemm_k<1,true ,false><<<gg, 256, GEMM_SMEM>>>(p1h, p1l, woh, wol,
            bout + vo, ftmp, op, nullptr, nullptr);
        prev = foutb;
    }
}

// round 14
// speedup vs baseline: 1.2531x; 1.0419x over previous
#include <cuda_runtime.h>
#include <cuda_bf16.h>
#include <math.h>
#include <stdint.h>

#define LYRS   2
#define HDIM   512
#define NHEAD  32
#define BATCH  8
#define SEQ    4096
#define MROWS  (BATCH*SEQ)
#define BLH    (MROWS*HDIM)

#define BM 128
#define BN 128
#define BK 64
#define STAGE_B 65536
#define SM_ST   1024
#define GEMM_SMEM (SM_ST + 3*STAGE_B)   /* 197632 */
#define LNTR_SMEM (512*33*4)            /* 67584 */

// ---------------- scratch ----------------------------------------------------
__device__ float Fo1[BLH], FoutB[BLH], Ftmp[BLH];
__device__ __nv_bfloat16 P0h[BLH], P0l[BLH], P1h[BLH], P1l[BLH], P2h[BLH], P2l[BLH];
__device__ __nv_bfloat16 WTh[10*HDIM*HDIM], WTl[10*HDIM*HDIM];
__device__ __nv_bfloat16 Gwh[LYRS*HDIM*HDIM], Gwl[LYRS*HDIM*HDIM];
__device__ float Bk1[LYRS*HDIM];
__device__ float Cb [LYRS*HDIM];
__device__ float Zb[HDIM];
__device__ float g_lam_re[LYRS*HDIM*NHEAD], g_lam_im[LYRS*HDIM*NHEAD];
__device__ float g_co_re [LYRS*HDIM*NHEAD], g_co_im [LYRS*HDIM*NHEAD];

// ---------------- PTX helpers --------------------------------------------------
__device__ __forceinline__ uint32_t smem_u32(const void* p) {
    uint32_t a;
    asm("{ .reg .u64 t; cvta.to.shared.u64 t, %1; cvt.u32.u64 %0, t; }"
        : "=r"(a) : "l"(p));
    return a;
}
#define CP16(dst, src) \
    asm volatile("cp.async.cg.shared.global [%0], [%1], 16;" \
        :: "r"(dst), "l"(src) : "memory")
#define CP_COMMIT() asm volatile("cp.async.commit_group;" ::: "memory")
#define CP_WAIT(n)  asm volatile("cp.async.wait_group %0;" :: "n"(n) : "memory")

#define LDSM_X4(r0,r1,r2,r3, addr) \
    asm volatile("ldmatrix.sync.aligned.m8n8.x4.shared.b16 {%0,%1,%2,%3}, [%4];" \
        : "=r"(r0),"=r"(r1),"=r"(r2),"=r"(r3) : "r"(addr))

#define MMA16816(d, a0,a1,a2,a3, b0,b1) \
    asm volatile("mma.sync.aligned.m16n8k16.row.col.f32.bf16.bf16.f32 " \
        "{%0,%1,%2,%3}, {%4,%5,%6,%7}, {%8,%9}, {%0,%1,%2,%3};" \
        : "+f"((d)[0]),"+f"((d)[1]),"+f"((d)[2]),"+f"((d)[3]) \
        : "r"(a0),"r"(a1),"r"(a2),"r"(a3), "r"(b0),"r"(b1))

__device__ __forceinline__ uint32_t swz(uint32_t off) { return off ^ ((off >> 3) & 0x70); }
__device__ __forceinline__ float gelu_f(float x) {
    return 0.5f * x * (1.0f + erff(x * 0.70710678118654752440f));
}
__device__ __forceinline__ void split_bf(float v, __nv_bfloat16& h, __nv_bfloat16& l) {
    h = __float2bfloat16(v);
    l = __float2bfloat16(v - __bfloat162float(h));
}

// ---------------- SSM coefficient precompute ----------------------------------
__global__ void prec_k(const float* __restrict__ log_dt,
                       const float* __restrict__ A_re, const float* __restrict__ A_im,
                       const float* __restrict__ B_re, const float* __restrict__ B_im,
                       const float* __restrict__ C_re, const float* __restrict__ C_im)
{
    int idx = blockIdx.x * blockDim.x + threadIdx.x;
    if (idx >= LYRS*HDIM*NHEAD) return;
    int lh = idx / NHEAD;
    float dt = expf(log_dt[lh]);
    float ar = A_re[idx], ai = A_im[idx];
    float e = expf(dt*ar);
    float sn, cs; sincosf(dt*ai, &sn, &cs);
    float lr = e*cs, li = e*sn;
    float nr = lr - 1.0f, ni = li;
    float inv = 1.0f/(ar*ar + ai*ai);
    float dr = (nr*ar + ni*ai)*inv;
    float di = (ni*ar - nr*ai)*inv;
    float br = B_re[idx], bi = B_im[idx];
    float dbr = br*dr - bi*di;
    float dbi = br*di + bi*dr;
    float cr = C_re[idx], ci = C_im[idx];
    g_co_re[idx] = 2.0f*(cr*dbr - ci*dbi);
    g_co_im[idx] = 2.0f*(cr*dbi + ci*dbr);
    g_lam_re[idx] = lr;
    g_lam_im[idx] = li;
}

// ---------------- weight transpose + hi/lo split --------------------------------
__global__ void wconv_k(const float* __restrict__ Wk, const float* __restrict__ W1,
                        const float* __restrict__ Wproj, const float* __restrict__ W2,
                        const float* __restrict__ Wout)
{
    int widx = blockIdx.z;
    int l = widx / 5, t = widx % 5;
    const float* src = (t==0 ? Wk : t==1 ? W1 : t==2 ? Wproj : t==3 ? W2 : Wout)
                       + (size_t)l * HDIM * HDIM;
    __shared__ float tile[32][33];
    int tx = threadIdx.x, ty = threadIdx.y;
    int n0 = blockIdx.x*32, k0 = blockIdx.y*32;
    #pragma unroll
    for (int i = 0; i < 4; ++i)
        tile[ty + 8*i][tx] = src[(size_t)(k0 + ty + 8*i)*HDIM + n0 + tx];
    __syncthreads();
    #pragma unroll
    for (int i = 0; i < 4; ++i) {
        float v = tile[tx][ty + 8*i];
        size_t o = (size_t)widx*HDIM*HDIM + (size_t)(n0 + ty + 8*i)*HDIM + k0 + tx;
        __nv_bfloat16 h, lo; split_bf(v, h, lo);
        WTh[o] = h; WTl[o] = lo;
    }
}

// ---------------- elementwise split of Wk --------------------------------------
__global__ void esplit_k(const float* __restrict__ Wk)
{
    int idx = blockIdx.x * blockDim.x + threadIdx.x;
    if (idx >= LYRS*HDIM*HDIM) return;
    __nv_bfloat16 h, lo; split_bf(Wk[idx], h, lo);
    Gwh[idx] = h; Gwl[idx] = lo;
}

// ---------------- fused biases: Bk1 = bk@W1 + b1 ; Cb = bout + bproj ------------
__global__ void __launch_bounds__(512)
bfuse_k(const float* __restrict__ bk, const float* __restrict__ b1,
        const float* __restrict__ W1,
        const float* __restrict__ bout, const float* __restrict__ bproj)
{
    __shared__ float red[4][128];
    const int l = blockIdx.x, nb = blockIdx.y;       // nb: 4 column chunks of 128
    const int n = threadIdx.x & 127;                 // column within chunk
    const int s = threadIdx.x >> 7;                  // j-slice 0..3
    const int col = nb*128 + n;
    const float* w = W1 + (size_t)l*HDIM*HDIM + col;
    const float* bb = bk + l*HDIM;
    float acc = 0.0f;
    for (int j = s*128; j < s*128 + 128; ++j)
        acc = fmaf(bb[j], w[(size_t)j*HDIM], acc);
    red[s][n] = acc;
    __syncthreads();
    if (s == 0) {
        float v = red[0][n] + red[1][n] + red[2][n] + red[3][n] + b1[l*HDIM + col];
        Bk1[l*HDIM + col] = v;
        Cb [l*HDIM + col] = bout[l*HDIM + col] + bproj[l*HDIM + col];
    }
}

// ---------------- fused LN1 + transpose: [B,L,H] fp32 -> LN -> [B,H,L] fp32 ----
__global__ void __launch_bounds__(256)
ln_tr_k(const float* __restrict__ src, const float* __restrict__ g,
        const float* __restrict__ b, float* __restrict__ dst)
{
    extern __shared__ float tile[];          // [512][33]
    __shared__ float mu_s[32], rs_s[32];
    const int tid = threadIdx.x;
    const int t0  = blockIdx.x * 32;
    const int bb  = blockIdx.y;
    const int wid = tid >> 5, lane = tid & 31;

    const float* sp = src + ((size_t)bb*SEQ + t0)*HDIM;
    const int r = tid >> 3, c8 = tid & 7;
    #pragma unroll
    for (int j = 0; j < 16; ++j) {
        int c4 = c8 + 8*j;
        float4 v = *(const float4*)(sp + (size_t)r*HDIM + c4*4);
        tile[(c4*4+0)*33 + r] = v.x;
        tile[(c4*4+1)*33 + r] = v.y;
        tile[(c4*4+2)*33 + r] = v.z;
        tile[(c4*4+3)*33 + r] = v.w;
    }
    __syncthreads();

    #pragma unroll
    for (int rr = wid*4; rr < wid*4 + 4; ++rr) {
        float s = 0.f, q = 0.f;
        #pragma unroll
        for (int j = 0; j < 16; ++j) {
            float v = tile[(lane + 32*j)*33 + rr];
            s += v; q += v*v;
        }
        #pragma unroll
        for (int o = 16; o; o >>= 1) {
            s += __shfl_xor_sync(0xffffffffu, s, o);
            q += __shfl_xor_sync(0xffffffffu, q, o);
        }
        if (lane == 0) {
            float mu = s * (1.0f/HDIM);
            mu_s[rr] = mu;
            rs_s[rr] = rsqrtf(q*(1.0f/HDIM) - mu*mu + 1e-5f);
        }
    }
    __syncthreads();

    float* dp = dst + (size_t)bb*HDIM*SEQ + t0;
    const int tq = tid & 7;
    #pragma unroll
    for (int j = 0; j < 16; ++j) {
        int h = (tid >> 3) + 32*j;
        float gv = __ldg(g + h), bv = __ldg(b + h);
        float4 o;
        o.x = (tile[h*33 + tq*4+0] - mu_s[tq*4+0])*rs_s[tq*4+0]*gv + bv;
        o.y = (tile[h*33 + tq*4+1] - mu_s[tq*4+1])*rs_s[tq*4+1]*gv + bv;
        o.z = (tile[h*33 + tq*4+2] - mu_s[tq*4+2])*rs_s[tq*4+2]*gv + bv;
        o.w = (tile[h*33 + tq*4+3] - mu_s[tq*4+3])*rs_s[tq*4+3]*gv + bv;
        *(float4*)(dp + (size_t)h*SEQ + tq*4) = o;
    }
}

// ---------------- LayerNorm: fp32 in -> bf16 hi/lo out --------------------------
__global__ void __launch_bounds__(128)
ln_k(const float* __restrict__ src, const float* __restrict__ g,
     const float* __restrict__ b,
     __nv_bfloat16* __restrict__ dsth, __nv_bfloat16* __restrict__ dstl)
{
    const int m = blockIdx.x, tid = threadIdx.x;
    const float4 v = *(const float4*)(src + (size_t)m*HDIM + tid*4);
    float s = v.x + v.y + v.z + v.w;
    float q = v.x*v.x + v.y*v.y + v.z*v.z + v.w*v.w;
    #pragma unroll
    for (int o = 16; o; o >>= 1) {
        s += __shfl_xor_sync(0xffffffffu, s, o);
        q += __shfl_xor_sync(0xffffffffu, q, o);
    }
    __shared__ float ss[4], qq[4], mu_s, rs_s;
    int w = tid >> 5;
    if ((tid & 31) == 0) { ss[w] = s; qq[w] = q; }
    __syncthreads();
    if (tid == 0) {
        float S = ss[0]+ss[1]+ss[2]+ss[3];
        float Q = qq[0]+qq[1]+qq[2]+qq[3];
        float mu = S*(1.0f/HDIM);
        mu_s = mu; rs_s = rsqrtf(Q*(1.0f/HDIM) - mu*mu + 1e-5f);
    }
    __syncthreads();
    const float mu = mu_s, rs = rs_s;
    const float4 gv = *(const float4*)(g + tid*4);
    const float4 bv = *(const float4*)(b + tid*4);
    float4 o;
    o.x = (v.x - mu)*rs*gv.x + bv.x;
    o.y = (v.y - mu)*rs*gv.y + bv.y;
    o.z = (v.z - mu)*rs*gv.z + bv.z;
    o.w = (v.w - mu)*rs*gv.w + bv.w;
    size_t off = (size_t)m*HDIM + tid*4;
    __nv_bfloat16 h0,h1,h2,h3,l0,l1,l2,l3;
    split_bf(o.x,h0,l0); split_bf(o.y,h1,l1);
    split_bf(o.z,h2,l2); split_bf(o.w,h3,l3);
    __nv_bfloat162 a0, a1, c0, c1;
    a0.x=h0; a0.y=h1; a1.x=h2; a1.y=h3;
    c0.x=l0; c0.y=l1; c1.x=l2; c1.y=l3;
    *(uint2*)(dsth + off) = make_uint2(*(uint32_t*)&a0, *(uint32_t*)&a1);
    *(uint2*)(dstl + off) = make_uint2(*(uint32_t*)&c0, *(uint32_t*)&c1);
}

// ---------------- S4 scan + D-skip + GELU (R11 proven version) ------------------
__global__ void __launch_bounds__(128)
scan_k(const float* __restrict__ zt, __nv_bfloat16* __restrict__ yh,
       __nv_bfloat16* __restrict__ yl, const float* __restrict__ Dvec, int l)
{
    __shared__ float st_s[4][32*36];
    __shared__ float zst[4][32];
    __shared__ float yt[2][32][9];
    const int tid  = threadIdx.x;
    const int wid  = tid >> 5;
    const int lane = tid & 31;
    const int b    = blockIdx.x >> 7;
    const int hg   = blockIdx.x & 127;
    const int h    = hg*4 + wid;
    const int base = l*HDIM*NHEAD + h*NHEAD + lane;
    const float lr = g_lam_re[base], li = g_lam_im[base];
    const float cr = g_co_re[base],  ci = g_co_im[base];
    const float nci = -ci;
    const float dsk = Dvec[h];
    const float* zp = zt + ((size_t)b*HDIM + h)*SEQ;
    float* st = st_s[wid];
    float* zs = zst[wid];
    const int ot = tid >> 2, oh = tid & 3;
    float sr = 0.0f, si = 0.0f;

    float zv = zp[lane];
    for (int t0 = 0; t0 < SEQ; t0 += 32) {
        float zv_next = (t0 + 32 < SEQ) ? zp[t0 + 32 + lane] : 0.0f;
        zs[lane] = zv;
        __syncwarp();
        #pragma unroll
        for (int tt = 0; tt < 32; ++tt) {
            float zv_t = zs[tt];
            float tmp  = fmaf(-li, si, zv_t);
            float nsi  = fmaf(li, sr, lr*si);
            sr = fmaf(lr, sr, tmp);
            si = nsi;
            st[tt*36 + lane] = fmaf(cr, sr, nci*si);
        }
        __syncwarp();
        float a0 = 0.f, a1 = 0.f, a2 = 0.f, a3 = 0.f;
        const float4* rp = (const float4*)&st[lane*36];
        #pragma unroll
        for (int i = 0; i < 8; ++i) {
            float4 v4 = rp[i];
            a0 += v4.x; a1 += v4.y; a2 += v4.z; a3 += v4.w;
        }
        const int buf = (t0 >> 5) & 1;
        yt[buf][lane][wid] = gelu_f((a0 + a1) + (a2 + a3) + dsk * zv);
        __syncthreads();
        float v = yt[buf][ot][oh];
        __nv_bfloat16 hh, ll; split_bf(v, hh, ll);
        size_t off = ((size_t)(b*SEQ + t0 + ot))*HDIM + hg*4 + oh;
        yh[off] = hh; yl[off] = ll;
        zv = zv_next;
    }
}

// ---------------- bf16x3 mma.sync GEMM: 3-stage, dual-source K ------------------
// A = [a | a2] (K up to 1024), W = [w ; w2]. nch = K/64.
template<int EPI, bool WF32, bool WHL>
__global__ void __launch_bounds__(256, 1)
tgemm_k(const __nv_bfloat16* __restrict__ ah, const __nv_bfloat16* __restrict__ al,
        const __nv_bfloat16* __restrict__ wh, const __nv_bfloat16* __restrict__ wl,
        const __nv_bfloat16* __restrict__ ah2, const __nv_bfloat16* __restrict__ al2,
        const __nv_bfloat16* __restrict__ wh2, const __nv_bfloat16* __restrict__ wl2,
        int nch,
        const float* __restrict__ bias, const float* __restrict__ res,
        float* __restrict__ outf,
        __nv_bfloat16* __restrict__ outh, __nv_bfloat16* __restrict__ outl)
{
    extern __shared__ __align__(1024) char smem[];
    const uint32_t sb = smem_u32(smem);
    const int tid  = threadIdx.x;
    const int wid  = tid >> 5;
    const int lane = tid & 31;
    const int wm   = wid & 1;
    const int wn   = wid >> 1;
    const int n0   = blockIdx.x * BN;
    const int m0   = blockIdx.y * BM;

    if (tid < BN) ((float*)smem)[tid] = bias[n0 + tid];

    const __nv_bfloat16* Ah = ah + (size_t)m0 * HDIM;
    const __nv_bfloat16* Al = al + (size_t)m0 * HDIM;
    const __nv_bfloat16* Wh = wh + (size_t)n0 * HDIM;
    const __nv_bfloat16* Wl = wl + (size_t)n0 * HDIM;
    const __nv_bfloat16* Ah2 = ah2 ? ah2 + (size_t)m0 * HDIM : nullptr;
    const __nv_bfloat16* Al2 = al2 ? al2 + (size_t)m0 * HDIM : nullptr;
    const __nv_bfloat16* Wh2 = wh2 ? wh2 + (size_t)n0 * HDIM : nullptr;
    const __nv_bfloat16* Wl2 = wl2 ? wl2 + (size_t)n0 * HDIM : nullptr;

    const int ldr = tid >> 3, ldc = tid & 7;
    auto load_chunk = [&](int ch, int st) {
        const uint32_t so = sb + SM_ST + st*STAGE_B;
        int cofs = ch * BK;
        const __nv_bfloat16 *A_h = Ah, *A_l = Al, *W_h = Wh, *W_l = Wl;
        if (cofs >= HDIM) {
            A_h = Ah2; A_l = Al2; W_h = Wh2; W_l = Wl2;
            cofs -= HDIM;
        }
        #pragma unroll
        for (int t = 0; t < 4; ++t) {
            int r = ldr + t*32;
            uint32_t dst = so + swz(r*128 + ldc*16);
            size_t gsrc = (size_t)r*HDIM + cofs + ldc*8;
            CP16(dst,         A_h + gsrc);
            CP16(dst + 16384, A_l + gsrc);
            CP16(dst + 32768, W_h + gsrc);
            CP16(dst + 49152, W_l + gsrc);
        }
        CP_COMMIT();
    };

    float acc[4][4][4];
    #pragma unroll
    for (int i = 0; i < 4; ++i)
        #pragma unroll
        for (int j = 0; j < 4; ++j)
            #pragma unroll
            for (int r = 0; r < 4; ++r) acc[i][j][r] = 0.0f;

    load_chunk(0, 0);
    load_chunk(1, 1);

    const int lr16 = lane & 15, lk = lane >> 4;
    for (int ch = 0; ch < nch; ++ch) {
        if (ch < nch-1) { CP_WAIT(1); } else { CP_WAIT(0); }
        __syncthreads();
        if (ch + 2 < nch) load_chunk(ch + 2, (ch + 2) % 3);
        const uint32_t so = sb + SM_ST + (ch % 3)*STAGE_B;
        #pragma unroll
        for (int kk = 0; kk < 4; ++kk) {
            const uint32_t ka = kk*32 + lk*16;
            uint32_t fah[4][4], fal[4][4];
            #pragma unroll
            for (int mi = 0; mi < 4; ++mi) {
                uint32_t ad = so + swz((wm*64 + mi*16 + lr16)*128 + ka);
                LDSM_X4(fah[mi][0], fah[mi][1], fah[mi][2], fah[mi][3], ad);
                LDSM_X4(fal[mi][0], fal[mi][1], fal[mi][2], fal[mi][3], ad + 16384);
            }
            uint32_t fbh[2][4], fbl[2][4];
            #pragma unroll
            for (int p = 0; p < 2; ++p) {
                uint32_t bd = so + 32768 + swz((wn*32 + p*16 + lr16)*128 + ka);
                LDSM_X4(fbh[p][0], fbh[p][1], fbh[p][2], fbh[p][3], bd);
                LDSM_X4(fbl[p][0], fbl[p][1], fbl[p][2], fbl[p][3], bd + 16384);
            }
            #pragma unroll
            for (int mi = 0; mi < 4; ++mi) {
                #pragma unroll
                for (int nj = 0; nj < 4; ++nj) {
                    const int p = nj >> 1, j = nj & 1;
                    MMA16816(acc[mi][nj], fah[mi][0], fah[mi][1], fah[mi][2], fah[mi][3],
                             fbh[p][j], fbh[p][j+2]);
                    MMA16816(acc[mi][nj], fah[mi][0], fah[mi][1], fah[mi][2], fah[mi][3],
                             fbl[p][j], fbl[p][j+2]);
                    MMA16816(acc[mi][nj], fal[mi][0], fal[mi][1], fal[mi][2], fal[mi][3],
                             fbh[p][j], fbh[p][j+2]);
                }
            }
        }
    }

    // ---------------- epilogue ----------------
    const float* bsm = (const float*)smem;
    const int rbase = m0 + wm*64;
    const int clb   = wn*32;
    #pragma unroll
    for (int mi = 0; mi < 4; ++mi) {
        #pragma unroll
        for (int nj = 0; nj < 4; ++nj) {
            const int ca = clb + nj*8 + (lane & 3)*2;
            const float b0 = bsm[ca], b1 = bsm[ca + 1];
            #pragma unroll
            for (int hrow = 0; hrow < 2; ++hrow) {
                const int r = rbase + mi*16 + (lane >> 2) + hrow*8;
                float v0 = acc[mi][nj][hrow*2 + 0] + b0;
                float v1 = acc[mi][nj][hrow*2 + 1] + b1;
                const size_t off = (size_t)r * HDIM + n0 + ca;
                if (EPI == 1) {
                    float2 rr = *(const float2*)(res + off);
                    v0 += rr.x; v1 += rr.y;
                }
                if (EPI == 2) { v0 = gelu_f(v0); v1 = gelu_f(v1); }
                if (WF32) *(float2*)(outf + off) = make_float2(v0, v1);
                if (WHL) {
                    __nv_bfloat16 h0, l0, h1, l1;
                    split_bf(v0, h0, l0); split_bf(v1, h1, l1);
                    __nv_bfloat162 hh, ll;
                    hh.x = h0; hh.y = h1; ll.x = l0; ll.y = l1;
                    *(uint32_t*)(outh + off) = *(uint32_t*)&hh;
                    *(uint32_t*)(outl + off) = *(uint32_t*)&ll;
                }
            }
        }
    }
}

// ---------------- orchestration --------------------------------------------------
extern "C" void kernel_launch(void* const* d_in, const int* in_sizes, int n_in,
                              void* d_out, int out_size)
{
    const float* x      = (const float*)d_in[0];
    const float* ln1w   = (const float*)d_in[1];
    const float* ln1b   = (const float*)d_in[2];
    const float* ln2w   = (const float*)d_in[3];
    const float* ln2b   = (const float*)d_in[4];
    const float* log_dt = (const float*)d_in[5];
    const float* A_re   = (const float*)d_in[6];
    const float* A_im   = (const float*)d_in[7];
    const float* B_re   = (const float*)d_in[8];
    const float* B_im   = (const float*)d_in[9];
    const float* C_re   = (const float*)d_in[10];
    const float* C_im   = (const float*)d_in[11];
    const float* Dv     = (const float*)d_in[12];
    const float* Wk     = (const float*)d_in[13];
    const float* bk     = (const float*)d_in[14];
    const float* W1     = (const float*)d_in[15];
    const float* b1     = (const float*)d_in[16];
    const float* W2     = (const float*)d_in[17];
    const float* b2     = (const float*)d_in[18];
    const float* Wout   = (const float*)d_in[19];
    const float* bout   = (const float*)d_in[20];
    const float* Wproj  = (const float*)d_in[21];
    const float* bproj  = (const float*)d_in[22];

    cudaFuncSetAttribute(tgemm_k<0,false,true >, cudaFuncAttributeMaxDynamicSharedMemorySize, GEMM_SMEM);
    cudaFuncSetAttribute(tgemm_k<1,true ,true >, cudaFuncAttributeMaxDynamicSharedMemorySize, GEMM_SMEM);
    cudaFuncSetAttribute(tgemm_k<0,true ,false>, cudaFuncAttributeMaxDynamicSharedMemorySize, GEMM_SMEM);
    cudaFuncSetAttribute(tgemm_k<2,false,true >, cudaFuncAttributeMaxDynamicSharedMemorySize, GEMM_SMEM);
    cudaFuncSetAttribute(ln_tr_k, cudaFuncAttributeMaxDynamicSharedMemorySize, LNTR_SMEM);

    float *fo1, *foutb, *zb, *bk1, *cb;
    __nv_bfloat16 *p0h, *p0l, *p1h, *p1l, *p2h, *p2l, *wth, *wtl, *gwh, *gwl;
    cudaGetSymbolAddress((void**)&fo1,  Fo1);
    cudaGetSymbolAddress((void**)&foutb,FoutB);
    cudaGetSymbolAddress((void**)&p0h,  P0h);
    cudaGetSymbolAddress((void**)&p0l,  P0l);
    cudaGetSymbolAddress((void**)&p1h,  P1h);
    cudaGetSymbolAddress((void**)&p1l,  P1l);
    cudaGetSymbolAddress((void**)&p2h,  P2h);
    cudaGetSymbolAddress((void**)&p2l,  P2l);
    cudaGetSymbolAddress((void**)&wth,  WTh);
    cudaGetSymbolAddress((void**)&wtl,  WTl);
    cudaGetSymbolAddress((void**)&gwh,  Gwh);
    cudaGetSymbolAddress((void**)&gwl,  Gwl);
    cudaGetSymbolAddress((void**)&zb,   Zb);
    cudaGetSymbolAddress((void**)&bk1,  Bk1);
    cudaGetSymbolAddress((void**)&cb,   Cb);

    float* ftmp;
    cudaGetSymbolAddress((void**)&ftmp, Ftmp);

    prec_k<<<(LYRS*HDIM*NHEAD + 255)/256, 256>>>(log_dt, A_re, A_im, B_re, B_im, C_re, C_im);
    wconv_k<<<dim3(16,16,10), dim3(32,8)>>>(Wk, W1, Wproj, W2, Wout);
    esplit_k<<<(LYRS*HDIM*HDIM + 255)/256, 256>>>(Wk);
    bfuse_k<<<dim3(LYRS,4), 512>>>(bk, b1, W1, bout, bproj);

    const size_t WB = (size_t)HDIM*HDIM;
    // Wk1^T[n][k] = sum_j W1^T[n][j] * Wk[k][j]  -> overwrite slot (l*5+0)
    for (int l = 0; l < LYRS; ++l) {
        tgemm_k<0,false,true><<<dim3(4,4), 256, GEMM_SMEM>>>(
            wth + (l*5+1)*WB, wtl + (l*5+1)*WB,
            gwh + l*WB,       gwl + l*WB,
            nullptr, nullptr, nullptr, nullptr, 8,
            zb, nullptr, nullptr,
            wth + (l*5+0)*WB, wtl + (l*5+0)*WB);
    }

    const dim3 gg(HDIM/BN, MROWS/BM);       // (4, 256)
    const float* prev = x;
    for (int l = 0; l < LYRS; ++l) {
        int vo = l * HDIM;
        const __nv_bfloat16 *wfh = wth + (l*5+0)*WB, *wfl = wtl + (l*5+0)*WB;
        const __nv_bfloat16 *wph = wth + (l*5+2)*WB, *wpl = wtl + (l*5+2)*WB;
        const __nv_bfloat16 *w2h = wth + (l*5+3)*WB, *w2l = wtl + (l*5+3)*WB;
        const __nv_bfloat16 *woh = wth + (l*5+4)*WB, *wol = wtl + (l*5+4)*WB;

        // zT = LN1(prev) transposed -> [B,H,L] fp32 (fused)
        ln_tr_k<<<dim3(SEQ/32, BATCH), 256, LNTR_SMEM>>>(prev, ln1w + vo, ln1b + vo, ftmp);
        // y = gelu(ssm(zT) + z*D) -> P0 hi/lo [B,L,H]
        scan_k<<<1024, 128>>>(ftmp, p0h, p0l, Dv + vo, l);
        // o1 = y @ (Wk@W1) + Bk1 + prev -> Fo1 fp32 + P1 hi/lo
        tgemm_k<1,true ,true ><<<gg, 256, GEMM_SMEM>>>(p0h, p0l, wfh, wfl,
            nullptr, nullptr, nullptr, nullptr, 8,
            bk1 + vo, prev, fo1, p1h, p1l);
        // z2 = LN2(o1) -> P0 hi/lo
        ln_k<<<MROWS, 128>>>(fo1, ln2w + vo, ln2b + vo, p0h, p0l);
        // h = gelu(z2 @ W2 + b2) -> P2 hi/lo
        tgemm_k<2,false,true ><<<gg, 256, GEMM_SMEM>>>(p0h, p0l, w2h, w2l,
            nullptr, nullptr, nullptr, nullptr, 8,
            b2 + vo, nullptr, nullptr, p2h, p2l);
        // out = [h|o1] @ [Wout;Wproj] + (bout+bproj) -> fp32 (merged K=1024)
        float* op = (l == LYRS-1) ? (float*)d_out : foutb;
        tgemm_k<0,true ,false><<<gg, 256, GEMM_SMEM>>>(p2h, p2l, woh, wol,
            p1h, p1l, wph, wpl, 16,
            cb + vo, nullptr, op, nullptr, nullptr);
        prev = foutb;
    }
}

// round 15
// speedup vs baseline: 1.5069x; 1.2026x over previous
#include <cuda_runtime.h>
#include <cuda_fp16.h>
#include <math.h>
#include <stdint.h>

#define LYRS   2
#define HDIM   512
#define NHEAD  32
#define BATCH  8
#define SEQ    4096
#define MROWS  (BATCH*SEQ)
#define BLH    (MROWS*HDIM)

#define BM 128
#define BN 128
#define BK 64
#define STAGE_B 49152               /* Ah16K + Al16K + W16K */
#define SM_ST   1024
#define GEMM_SMEM (SM_ST + 3*STAGE_B)   /* 148480 */
#define LNTR_SMEM (512*33*4)            /* 67584 */

// ---------------- scratch ----------------------------------------------------
__device__ float Fo1[BLH], FoutB[BLH], Ftmp[BLH];
__device__ __half P0h[BLH], P0l[BLH], P1h[BLH], P1l[BLH], P2h[BLH], P2l[BLH];
__device__ __half WTh[10*HDIM*HDIM], WTl[10*HDIM*HDIM];
__device__ __half Gw[LYRS*HDIM*HDIM];
__device__ float Bk1[LYRS*HDIM];
__device__ float Cb [LYRS*HDIM];
__device__ float Zb[HDIM];
__device__ float g_lam_re[LYRS*HDIM*NHEAD], g_lam_im[LYRS*HDIM*NHEAD];
__device__ float g_co_re [LYRS*HDIM*NHEAD], g_co_im [LYRS*HDIM*NHEAD];

// ---------------- PTX helpers --------------------------------------------------
__device__ __forceinline__ uint32_t smem_u32(const void* p) {
    uint32_t a;
    asm("{ .reg .u64 t; cvta.to.shared.u64 t, %1; cvt.u32.u64 %0, t; }"
        : "=r"(a) : "l"(p));
    return a;
}
#define CP16(dst, src) \
    asm volatile("cp.async.cg.shared.global [%0], [%1], 16;" \
        :: "r"(dst), "l"(src) : "memory")
#define CP_COMMIT() asm volatile("cp.async.commit_group;" ::: "memory")
#define CP_WAIT(n)  asm volatile("cp.async.wait_group %0;" :: "n"(n) : "memory")

#define LDSM_X4(r0,r1,r2,r3, addr) \
    asm volatile("ldmatrix.sync.aligned.m8n8.x4.shared.b16 {%0,%1,%2,%3}, [%4];" \
        : "=r"(r0),"=r"(r1),"=r"(r2),"=r"(r3) : "r"(addr))

#define MMA16816(d, a0,a1,a2,a3, b0,b1) \
    asm volatile("mma.sync.aligned.m16n8k16.row.col.f32.f16.f16.f32 " \
        "{%0,%1,%2,%3}, {%4,%5,%6,%7}, {%8,%9}, {%0,%1,%2,%3};" \
        : "+f"((d)[0]),"+f"((d)[1]),"+f"((d)[2]),"+f"((d)[3]) \
        : "r"(a0),"r"(a1),"r"(a2),"r"(a3), "r"(b0),"r"(b1))

__device__ __forceinline__ uint32_t swz(uint32_t off) { return off ^ ((off >> 3) & 0x70); }
__device__ __forceinline__ float gelu_f(float x) {
    return 0.5f * x * (1.0f + erff(x * 0.70710678118654752440f));
}
__device__ __forceinline__ void split_hf(float v, __half& h, __half& l) {
    h = __float2half(v);
    l = __float2half(v - __half2float(h));
}

// ---------------- SSM coefficient precompute ----------------------------------
__global__ void prec_k(const float* __restrict__ log_dt,
                       const float* __restrict__ A_re, const float* __restrict__ A_im,
                       const float* __restrict__ B_re, const float* __restrict__ B_im,
                       const float* __restrict__ C_re, const float* __restrict__ C_im)
{
    int idx = blockIdx.x * blockDim.x + threadIdx.x;
    if (idx >= LYRS*HDIM*NHEAD) return;
    int lh = idx / NHEAD;
    float dt = expf(log_dt[lh]);
    float ar = A_re[idx], ai = A_im[idx];
    float e = expf(dt*ar);
    float sn, cs; sincosf(dt*ai, &sn, &cs);
    float lr = e*cs, li = e*sn;
    float nr = lr - 1.0f, ni = li;
    float inv = 1.0f/(ar*ar + ai*ai);
    float dr = (nr*ar + ni*ai)*inv;
    float di = (ni*ar - nr*ai)*inv;
    float br = B_re[idx], bi = B_im[idx];
    float dbr = br*dr - bi*di;
    float dbi = br*di + bi*dr;
    float cr = C_re[idx], ci = C_im[idx];
    g_co_re[idx] = 2.0f*(cr*dbr - ci*dbi);
    g_co_im[idx] = 2.0f*(cr*dbi + ci*dbr);
    g_lam_re[idx] = lr;
    g_lam_im[idx] = li;
}

// ---------------- weight transpose + fp16 hi/lo split ---------------------------
__global__ void wconv_k(const float* __restrict__ Wk, const float* __restrict__ W1,
                        const float* __restrict__ Wproj, const float* __restrict__ W2,
                        const float* __restrict__ Wout)
{
    int widx = blockIdx.z;
    int l = widx / 5, t = widx % 5;
    const float* src = (t==0 ? Wk : t==1 ? W1 : t==2 ? Wproj : t==3 ? W2 : Wout)
                       + (size_t)l * HDIM * HDIM;
    __shared__ float tile[32][33];
    int tx = threadIdx.x, ty = threadIdx.y;
    int n0 = blockIdx.x*32, k0 = blockIdx.y*32;
    #pragma unroll
    for (int i = 0; i < 4; ++i)
        tile[ty + 8*i][tx] = src[(size_t)(k0 + ty + 8*i)*HDIM + n0 + tx];
    __syncthreads();
    #pragma unroll
    for (int i = 0; i < 4; ++i) {
        float v = tile[tx][ty + 8*i];
        size_t o = (size_t)widx*HDIM*HDIM + (size_t)(n0 + ty + 8*i)*HDIM + k0 + tx;
        __half h, lo; split_hf(v, h, lo);
        WTh[o] = h; WTl[o] = lo;
    }
}

// ---------------- elementwise fp16 of Wk ----------------------------------------
__global__ void esplit_k(const float* __restrict__ Wk)
{
    int idx = blockIdx.x * blockDim.x + threadIdx.x;
    if (idx >= LYRS*HDIM*HDIM) return;
    Gw[idx] = __float2half(Wk[idx]);
}

// ---------------- fused biases (warp-per-column, coalesced via W1^T) ------------
__global__ void __launch_bounds__(256)
bfuse_k(const float* __restrict__ bk, const float* __restrict__ b1,
        const float* __restrict__ bout, const float* __restrict__ bproj)
{
    const int l = blockIdx.x;
    const int n = blockIdx.y*8 + (threadIdx.x >> 5);
    const int lane = threadIdx.x & 31;
    const __half* wh = WTh + ((size_t)(l*5+1))*HDIM*HDIM + (size_t)n*HDIM;
    const __half* wl = WTl + ((size_t)(l*5+1))*HDIM*HDIM + (size_t)n*HDIM;
    const float* bb = bk + l*HDIM;
    float acc = 0.0f;
    #pragma unroll
    for (int i = 0; i < 16; ++i) {
        int j = lane + 32*i;
        acc = fmaf(bb[j], __half2float(wh[j]) + __half2float(wl[j]), acc);
    }
    #pragma unroll
    for (int o = 16; o; o >>= 1) acc += __shfl_xor_sync(0xffffffffu, acc, o);
    if (lane == 0) {
        Bk1[l*HDIM + n] = acc + b1[l*HDIM + n];
        Cb [l*HDIM + n] = bout[l*HDIM + n] + bproj[l*HDIM + n];
    }
}

// ---------------- fused LN1 + transpose: [B,L,H] fp32 -> LN -> [B,H,L] fp32 ----
__global__ void __launch_bounds__(256)
ln_tr_k(const float* __restrict__ src, const float* __restrict__ g,
        const float* __restrict__ b, float* __restrict__ dst)
{
    extern __shared__ float tile[];          // [512][33]
    __shared__ float mu_s[32], rs_s[32];
    const int tid = threadIdx.x;
    const int t0  = blockIdx.x * 32;
    const int bb  = blockIdx.y;
    const int wid = tid >> 5, lane = tid & 31;

    const float* sp = src + ((size_t)bb*SEQ + t0)*HDIM;
    const int r = tid >> 3, c8 = tid & 7;
    #pragma unroll
    for (int j = 0; j < 16; ++j) {
        int c4 = c8 + 8*j;
        float4 v = *(const float4*)(sp + (size_t)r*HDIM + c4*4);
        tile[(c4*4+0)*33 + r] = v.x;
        tile[(c4*4+1)*33 + r] = v.y;
        tile[(c4*4+2)*33 + r] = v.z;
        tile[(c4*4+3)*33 + r] = v.w;
    }
    __syncthreads();

    #pragma unroll
    for (int rr = wid*4; rr < wid*4 + 4; ++rr) {
        float s = 0.f, q = 0.f;
        #pragma unroll
        for (int j = 0; j < 16; ++j) {
            float v = tile[(lane + 32*j)*33 + rr];
            s += v; q += v*v;
        }
        #pragma unroll
        for (int o = 16; o; o >>= 1) {
            s += __shfl_xor_sync(0xffffffffu, s, o);
            q += __shfl_xor_sync(0xffffffffu, q, o);
        }
        if (lane == 0) {
            float mu = s * (1.0f/HDIM);
            mu_s[rr] = mu;
            rs_s[rr] = rsqrtf(q*(1.0f/HDIM) - mu*mu + 1e-5f);
        }
    }
    __syncthreads();

    float* dp = dst + (size_t)bb*HDIM*SEQ + t0;
    const int tq = tid & 7;
    #pragma unroll
    for (int j = 0; j < 16; ++j) {
        int h = (tid >> 3) + 32*j;
        float gv = __ldg(g + h), bv = __ldg(b + h);
        float4 o;
        o.x = (tile[h*33 + tq*4+0] - mu_s[tq*4+0])*rs_s[tq*4+0]*gv + bv;
        o.y = (tile[h*33 + tq*4+1] - mu_s[tq*4+1])*rs_s[tq*4+1]*gv + bv;
        o.z = (tile[h*33 + tq*4+2] - mu_s[tq*4+2])*rs_s[tq*4+2]*gv + bv;
        o.w = (tile[h*33 + tq*4+3] - mu_s[tq*4+3])*rs_s[tq*4+3]*gv + bv;
        *(float4*)(dp + (size_t)h*SEQ + tq*4) = o;
    }
}

// ---------------- LayerNorm: fp32 in -> fp16 hi/lo out --------------------------
__global__ void __launch_bounds__(128)
ln_k(const float* __restrict__ src, const float* __restrict__ g,
     const float* __restrict__ b,
     __half* __restrict__ dsth, __half* __restrict__ dstl)
{
    const int m = blockIdx.x, tid = threadIdx.x;
    const float4 v = *(const float4*)(src + (size_t)m*HDIM + tid*4);
    float s = v.x + v.y + v.z + v.w;
    float q = v.x*v.x + v.y*v.y + v.z*v.z + v.w*v.w;
    #pragma unroll
    for (int o = 16; o; o >>= 1) {
        s += __shfl_xor_sync(0xffffffffu, s, o);
        q += __shfl_xor_sync(0xffffffffu, q, o);
    }
    __shared__ float ss[4], qq[4], mu_s, rs_s;
    int w = tid >> 5;
    if ((tid & 31) == 0) { ss[w] = s; qq[w] = q; }
    __syncthreads();
    if (tid == 0) {
        float S = ss[0]+ss[1]+ss[2]+ss[3];
        float Q = qq[0]+qq[1]+qq[2]+qq[3];
        float mu = S*(1.0f/HDIM);
        mu_s = mu; rs_s = rsqrtf(Q*(1.0f/HDIM) - mu*mu + 1e-5f);
    }
    __syncthreads();
    const float mu = mu_s, rs = rs_s;
    const float4 gv = *(const float4*)(g + tid*4);
    const float4 bv = *(const float4*)(b + tid*4);
    float4 o;
    o.x = (v.x - mu)*rs*gv.x + bv.x;
    o.y = (v.y - mu)*rs*gv.y + bv.y;
    o.z = (v.z - mu)*rs*gv.z + bv.z;
    o.w = (v.w - mu)*rs*gv.w + bv.w;
    size_t off = (size_t)m*HDIM + tid*4;
    __half h0,h1,h2,h3,l0,l1,l2,l3;
    split_hf(o.x,h0,l0); split_hf(o.y,h1,l1);
    split_hf(o.z,h2,l2); split_hf(o.w,h3,l3);
    __half2 a0 = __halves2half2(h0,h1), a1 = __halves2half2(h2,h3);
    __half2 c0 = __halves2half2(l0,l1), c1 = __halves2half2(l2,l3);
    *(uint2*)(dsth + off) = make_uint2(*(uint32_t*)&a0, *(uint32_t*)&a1);
    *(uint2*)(dstl + off) = make_uint2(*(uint32_t*)&c0, *(uint32_t*)&c1);
}

// ---------------- S4 scan + D-skip + GELU ---------------------------------------
__global__ void __launch_bounds__(128)
scan_k(const float* __restrict__ zt, __half* __restrict__ yh,
       __half* __restrict__ yl, const float* __restrict__ Dvec, int l)
{
    __shared__ float st_s[4][32*36];
    __shared__ float zst[4][32];
    __shared__ float yt[2][32][9];
    const int tid  = threadIdx.x;
    const int wid  = tid >> 5;
    const int lane = tid & 31;
    const int b    = blockIdx.x >> 7;
    const int hg   = blockIdx.x & 127;
    const int h    = hg*4 + wid;
    const int base = l*HDIM*NHEAD + h*NHEAD + lane;
    const float lr = g_lam_re[base], li = g_lam_im[base];
    const float cr = g_co_re[base],  ci = g_co_im[base];
    const float nci = -ci;
    const float dsk = Dvec[h];
    const float* zp = zt + ((size_t)b*HDIM + h)*SEQ;
    float* st = st_s[wid];
    float* zs = zst[wid];
    const int ot = tid >> 2, oh = tid & 3;
    float sr = 0.0f, si = 0.0f;

    float zv = zp[lane];
    for (int t0 = 0; t0 < SEQ; t0 += 32) {
        float zv_next = (t0 + 32 < SEQ) ? zp[t0 + 32 + lane] : 0.0f;
        zs[lane] = zv;
        __syncwarp();
        #pragma unroll
        for (int tt = 0; tt < 32; ++tt) {
            float zv_t = zs[tt];
            float tmp  = fmaf(-li, si, zv_t);
            float nsi  = fmaf(li, sr, lr*si);
            sr = fmaf(lr, sr, tmp);
            si = nsi;
            st[tt*36 + lane] = fmaf(cr, sr, nci*si);
        }
        __syncwarp();
        float a0 = 0.f, a1 = 0.f, a2 = 0.f, a3 = 0.f;
        const float4* rp = (const float4*)&st[lane*36];
        #pragma unroll
        for (int i = 0; i < 8; ++i) {
            float4 v4 = rp[i];
            a0 += v4.x; a1 += v4.y; a2 += v4.z; a3 += v4.w;
        }
        const int buf = (t0 >> 5) & 1;
        yt[buf][lane][wid] = gelu_f((a0 + a1) + (a2 + a3) + dsk * zv);
        __syncthreads();
        float v = yt[buf][ot][oh];
        __half hh, ll; split_hf(v, hh, ll);
        size_t off = ((size_t)(b*SEQ + t0 + ot))*HDIM + hg*4 + oh;
        yh[off] = hh; yl[off] = ll;
        zv = zv_next;
    }
}

// ---------------- fp16x2 mma.sync GEMM: A hi/lo exact, W single fp16 ------------
// A = [a | a2] (K up to 1024), W = [w ; w2]. nch = K/64.
template<int EPI, bool WF32, bool WHL>
__global__ void __launch_bounds__(256, 1)
tgemm_k(const __half* __restrict__ ah, const __half* __restrict__ al,
        const __half* __restrict__ wq,
        const __half* __restrict__ ah2, const __half* __restrict__ al2,
        const __half* __restrict__ wq2,
        int nch,
        const float* __restrict__ bias, const float* __restrict__ res,
        float* __restrict__ outf,
        __half* __restrict__ outh, __half* __restrict__ outl)
{
    extern __shared__ __align__(1024) char smem[];
    const uint32_t sb = smem_u32(smem);
    const int tid  = threadIdx.x;
    const int wid  = tid >> 5;
    const int lane = tid & 31;
    const int wm   = wid & 1;
    const int wn   = wid >> 1;
    const int n0   = blockIdx.x * BN;
    const int m0   = blockIdx.y * BM;

    if (tid < BN) ((float*)smem)[tid] = bias[n0 + tid];

    const __half* Ah = ah + (size_t)m0 * HDIM;
    const __half* Al = al + (size_t)m0 * HDIM;
    const __half* Wq = wq + (size_t)n0 * HDIM;
    const __half* Ah2 = ah2 ? ah2 + (size_t)m0 * HDIM : nullptr;
    const __half* Al2 = al2 ? al2 + (size_t)m0 * HDIM : nullptr;
    const __half* Wq2 = wq2 ? wq2 + (size_t)n0 * HDIM : nullptr;

    const int ldr = tid >> 3, ldc = tid & 7;
    auto load_chunk = [&](int ch, int st) {
        const uint32_t so = sb + SM_ST + st*STAGE_B;
        int cofs = ch * BK;
        const __half *A_h = Ah, *A_l = Al, *W_q = Wq;
        if (cofs >= HDIM) {
            A_h = Ah2; A_l = Al2; W_q = Wq2;
            cofs -= HDIM;
        }
        #pragma unroll
        for (int t = 0; t < 4; ++t) {
            int r = ldr + t*32;
            uint32_t dst = so + swz(r*128 + ldc*16);
            size_t gsrc = (size_t)r*HDIM + cofs + ldc*8;
            CP16(dst,         A_h + gsrc);
            CP16(dst + 16384, A_l + gsrc);
            CP16(dst + 32768, W_q + gsrc);
        }
        CP_COMMIT();
    };

    float acc[4][4][4];
    #pragma unroll
    for (int i = 0; i < 4; ++i)
        #pragma unroll
        for (int j = 0; j < 4; ++j)
            #pragma unroll
            for (int r = 0; r < 4; ++r) acc[i][j][r] = 0.0f;

    load_chunk(0, 0);
    load_chunk(1, 1);

    const int lr16 = lane & 15, lk = lane >> 4;
    for (int ch = 0; ch < nch; ++ch) {
        if (ch < nch-1) { CP_WAIT(1); } else { CP_WAIT(0); }
        __syncthreads();
        if (ch + 2 < nch) load_chunk(ch + 2, (ch + 2) % 3);
        const uint32_t so = sb + SM_ST + (ch % 3)*STAGE_B;
        #pragma unroll
        for (int kk = 0; kk < 4; ++kk) {
            const uint32_t ka = kk*32 + lk*16;
            uint32_t fah[4][4], fal[4][4];
            #pragma unroll
            for (int mi = 0; mi < 4; ++mi) {
                uint32_t ad = so + swz((wm*64 + mi*16 + lr16)*128 + ka);
                LDSM_X4(fah[mi][0], fah[mi][1], fah[mi][2], fah[mi][3], ad);
                LDSM_X4(fal[mi][0], fal[mi][1], fal[mi][2], fal[mi][3], ad + 16384);
            }
            uint32_t fb[2][4];
            #pragma unroll
            for (int p = 0; p < 2; ++p) {
                uint32_t bd = so + 32768 + swz((wn*32 + p*16 + lr16)*128 + ka);
                LDSM_X4(fb[p][0], fb[p][1], fb[p][2], fb[p][3], bd);
            }
            #pragma unroll
            for (int mi = 0; mi < 4; ++mi) {
                #pragma unroll
                for (int nj = 0; nj < 4; ++nj) {
                    const int p = nj >> 1, j = nj & 1;
                    MMA16816(acc[mi][nj], fah[mi][0], fah[mi][1], fah[mi][2], fah[mi][3],
                             fb[p][j], fb[p][j+2]);
                    MMA16816(acc[mi][nj], fal[mi][0], fal[mi][1], fal[mi][2], fal[mi][3],
                             fb[p][j], fb[p][j+2]);
                }
            }
        }
    }

    // ---------------- epilogue ----------------
    const float* bsm = (const float*)smem;
    const int rbase = m0 + wm*64;
    const int clb   = wn*32;
    #pragma unroll
    for (int mi = 0; mi < 4; ++mi) {
        #pragma unroll
        for (int nj = 0; nj < 4; ++nj) {
            const int ca = clb + nj*8 + (lane & 3)*2;
            const float b0 = bsm[ca], b1 = bsm[ca + 1];
            #pragma unroll
            for (int hrow = 0; hrow < 2; ++hrow) {
                const int r = rbase + mi*16 + (lane >> 2) + hrow*8;
                float v0 = acc[mi][nj][hrow*2 + 0] + b0;
                float v1 = acc[mi][nj][hrow*2 + 1] + b1;
                const size_t off = (size_t)r * HDIM + n0 + ca;
                if (EPI == 1) {
                    float2 rr = *(const float2*)(res + off);
                    v0 += rr.x; v1 += rr.y;
                }
                if (EPI == 2) { v0 = gelu_f(v0); v1 = gelu_f(v1); }
                if (WF32) *(float2*)(outf + off) = make_float2(v0, v1);
                if (WHL) {
                    __half h0, l0, h1, l1;
                    split_hf(v0, h0, l0); split_hf(v1, h1, l1);
                    __half2 hh = __halves2half2(h0, h1);
                    __half2 ll = __halves2half2(l0, l1);
                    *(uint32_t*)(outh + off) = *(uint32_t*)&hh;
                    *(uint32_t*)(outl + off) = *(uint32_t*)&ll;
                }
            }
        }
    }
}

// ---------------- orchestration --------------------------------------------------
extern "C" void kernel_launch(void* const* d_in, const int* in_sizes, int n_in,
                              void* d_out, int out_size)
{
    const float* x      = (const float*)d_in[0];
    const float* ln1w   = (const float*)d_in[1];
    const float* ln1b   = (const float*)d_in[2];
    const float* ln2w   = (const float*)d_in[3];
    const float* ln2b   = (const float*)d_in[4];
    const float* log_dt = (const float*)d_in[5];
    const float* A_re   = (const float*)d_in[6];
    const float* A_im   = (const float*)d_in[7];
    const float* B_re   = (const float*)d_in[8];
    const float* B_im   = (const float*)d_in[9];
    const float* C_re   = (const float*)d_in[10];
    const float* C_im   = (const float*)d_in[11];
    const float* Dv     = (const float*)d_in[12];
    const float* Wk     = (const float*)d_in[13];
    const float* bk     = (const float*)d_in[14];
    const float* W1     = (const float*)d_in[15];
    const float* b1     = (const float*)d_in[16];
    const float* W2     = (const float*)d_in[17];
    const float* b2     = (const float*)d_in[18];
    const float* Wout   = (const float*)d_in[19];
    const float* bout   = (const float*)d_in[20];
    const float* Wproj  = (const float*)d_in[21];
    const float* bproj  = (const float*)d_in[22];

    cudaFuncSetAttribute(tgemm_k<0,false,true >, cudaFuncAttributeMaxDynamicSharedMemorySize, GEMM_SMEM);
    cudaFuncSetAttribute(tgemm_k<1,true ,true >, cudaFuncAttributeMaxDynamicSharedMemorySize, GEMM_SMEM);
    cudaFuncSetAttribute(tgemm_k<0,true ,false>, cudaFuncAttributeMaxDynamicSharedMemorySize, GEMM_SMEM);
    cudaFuncSetAttribute(tgemm_k<2,false,true >, cudaFuncAttributeMaxDynamicSharedMemorySize, GEMM_SMEM);
    cudaFuncSetAttribute(ln_tr_k, cudaFuncAttributeMaxDynamicSharedMemorySize, LNTR_SMEM);

    float *fo1, *foutb, *ftmp, *zb, *bk1, *cb;
    __half *p0h, *p0l, *p1h, *p1l, *p2h, *p2l, *wth, *wtl, *gw;
    cudaGetSymbolAddress((void**)&fo1,  Fo1);
    cudaGetSymbolAddress((void**)&foutb,FoutB);
    cudaGetSymbolAddress((void**)&ftmp, Ftmp);
    cudaGetSymbolAddress((void**)&p0h,  P0h);
    cudaGetSymbolAddress((void**)&p0l,  P0l);
    cudaGetSymbolAddress((void**)&p1h,  P1h);
    cudaGetSymbolAddress((void**)&p1l,  P1l);
    cudaGetSymbolAddress((void**)&p2h,  P2h);
    cudaGetSymbolAddress((void**)&p2l,  P2l);
    cudaGetSymbolAddress((void**)&wth,  WTh);
    cudaGetSymbolAddress((void**)&wtl,  WTl);
    cudaGetSymbolAddress((void**)&gw,   Gw);
    cudaGetSymbolAddress((void**)&zb,   Zb);
    cudaGetSymbolAddress((void**)&bk1,  Bk1);
    cudaGetSymbolAddress((void**)&cb,   Cb);

    prec_k<<<(LYRS*HDIM*NHEAD + 255)/256, 256>>>(log_dt, A_re, A_im, B_re, B_im, C_re, C_im);
    wconv_k<<<dim3(16,16,10), dim3(32,8)>>>(Wk, W1, Wproj, W2, Wout);
    esplit_k<<<(LYRS*HDIM*HDIM + 255)/256, 256>>>(Wk);
    bfuse_k<<<dim3(LYRS,64), 256>>>(bk, b1, bout, bproj);

    const size_t WB = (size_t)HDIM*HDIM;
    // Wk1^T[n][k] = sum_j W1^T[n][j] * Wk[k][j]  -> overwrite slot (l*5+0)
    for (int l = 0; l < LYRS; ++l) {
        tgemm_k<0,false,true><<<dim3(4,4), 256, GEMM_SMEM>>>(
            wth + (l*5+1)*WB, wtl + (l*5+1)*WB,
            gw + l*WB,
            nullptr, nullptr, nullptr, 8,
            zb, nullptr, nullptr,
            wth + (l*5+0)*WB, wtl + (l*5+0)*WB);
    }

    const dim3 gg(HDIM/BN, MROWS/BM);       // (4, 256)
    const float* prev = x;
    for (int l = 0; l < LYRS; ++l) {
        int vo = l * HDIM;
        const __half *wf = wth + (l*5+0)*WB;   // fused Wk@W1 (fp16)
        const __half *wp = wth + (l*5+2)*WB;
        const __half *w2 = wth + (l*5+3)*WB;
        const __half *wo = wth + (l*5+4)*WB;

        // zT = LN1(prev) transposed -> [B,H,L] fp32 (fused)
        ln_tr_k<<<dim3(SEQ/32, BATCH), 256, LNTR_SMEM>>>(prev, ln1w + vo, ln1b + vo, ftmp);
        // y = gelu(ssm(zT) + z*D) -> P0 hi/lo [B,L,H]
        scan_k<<<1024, 128>>>(ftmp, p0h, p0l, Dv + vo, l);
        // o1 = y @ (Wk@W1) + Bk1 + prev -> Fo1 fp32 + P1 hi/lo
        tgemm_k<1,true ,true ><<<gg, 256, GEMM_SMEM>>>(p0h, p0l, wf,
            nullptr, nullptr, nullptr, 8,
            bk1 + vo, prev, fo1, p1h, p1l);
        // z2 = LN2(o1) -> P0 hi/lo
        ln_k<<<MROWS, 128>>>(fo1, ln2w + vo, ln2b + vo, p0h, p0l);
        // h = gelu(z2 @ W2 + b2) -> P2 hi/lo
        tgemm_k<2,false,true ><<<gg, 256, GEMM_SMEM>>>(p0h, p0l, w2,
            nullptr, nullptr, nullptr, 8,
            b2 + vo, nullptr, nullptr, p2h, p2l);
        // out = [h|o1] @ [Wout;Wproj] + (bout+bproj) -> fp32 (merged K=1024)
        float* op = (l == LYRS-1) ? (float*)d_out : foutb;
        tgemm_k<0,true ,false><<<gg, 256, GEMM_SMEM>>>(p2h, p2l, wo,
            p1h, p1l, wp, 16,
            cb + vo, nullptr, op, nullptr, nullptr);
        prev = foutb;
    }
}

// round 16
// speedup vs baseline: 1.6581x; 1.1003x over previous
#include <cuda_runtime.h>
#include <cuda_fp16.h>
#include <math.h>
#include <stdint.h>

#define LYRS   2
#define HDIM   512
#define NHEAD  32
#define BATCH  8
#define SEQ    4096
#define MROWS  (BATCH*SEQ)
#define BLH    (MROWS*HDIM)

#define BM 128
#define BN 128
#define BK 64
#define STAGE_B 49152               /* Ah16K + Al16K + W16K */
#define SM_ST   1024
#define GEMM_SMEM (SM_ST + 2*STAGE_B)   /* 99328 -> 2 CTAs/SM */
#define LNTR_SMEM (512*33*4)            /* 67584 */

// ---------------- scratch ----------------------------------------------------
__device__ float Fo1[BLH], FoutB[BLH], Ftmp[BLH];
__device__ __half P0h[BLH], P0l[BLH], P1h[BLH], P1l[BLH], P2h[BLH], P2l[BLH];
__device__ __half WTh[10*HDIM*HDIM], WTl[10*HDIM*HDIM];
__device__ __half Gw[LYRS*HDIM*HDIM];
__device__ float Bk1[LYRS*HDIM];
__device__ float Cb [LYRS*HDIM];
__device__ float Zb[HDIM];
__device__ float g_lam_re[LYRS*HDIM*NHEAD], g_lam_im[LYRS*HDIM*NHEAD];
__device__ float g_co_re [LYRS*HDIM*NHEAD], g_co_im [LYRS*HDIM*NHEAD];

// ---------------- PTX helpers --------------------------------------------------
__device__ __forceinline__ uint32_t smem_u32(const void* p) {
    uint32_t a;
    asm("{ .reg .u64 t; cvta.to.shared.u64 t, %1; cvt.u32.u64 %0, t; }"
        : "=r"(a) : "l"(p));
    return a;
}
#define CP16(dst, src) \
    asm volatile("cp.async.cg.shared.global [%0], [%1], 16;" \
        :: "r"(dst), "l"(src) : "memory")
#define CP_COMMIT() asm volatile("cp.async.commit_group;" ::: "memory")
#define CP_WAIT(n)  asm volatile("cp.async.wait_group %0;" :: "n"(n) : "memory")

#define LDSM_X4(r0,r1,r2,r3, addr) \
    asm volatile("ldmatrix.sync.aligned.m8n8.x4.shared.b16 {%0,%1,%2,%3}, [%4];" \
        : "=r"(r0),"=r"(r1),"=r"(r2),"=r"(r3) : "r"(addr))

#define MMA16816(d, a0,a1,a2,a3, b0,b1) \
    asm volatile("mma.sync.aligned.m16n8k16.row.col.f32.f16.f16.f32 " \
        "{%0,%1,%2,%3}, {%4,%5,%6,%7}, {%8,%9}, {%0,%1,%2,%3};" \
        : "+f"((d)[0]),"+f"((d)[1]),"+f"((d)[2]),"+f"((d)[3]) \
        : "r"(a0),"r"(a1),"r"(a2),"r"(a3), "r"(b0),"r"(b1))

__device__ __forceinline__ uint32_t swz(uint32_t off) { return off ^ ((off >> 3) & 0x70); }
__device__ __forceinline__ float gelu_f(float x) {
    return 0.5f * x * (1.0f + erff(x * 0.70710678118654752440f));
}
__device__ __forceinline__ void split_hf(float v, __half& h, __half& l) {
    h = __float2half(v);
    l = __float2half(v - __half2float(h));
}

// ---------------- SSM coefficient precompute ----------------------------------
__global__ void prec_k(const float* __restrict__ log_dt,
                       const float* __restrict__ A_re, const float* __restrict__ A_im,
                       const float* __restrict__ B_re, const float* __restrict__ B_im,
                       const float* __restrict__ C_re, const float* __restrict__ C_im)
{
    int idx = blockIdx.x * blockDim.x + threadIdx.x;
    if (idx >= LYRS*HDIM*NHEAD) return;
    int lh = idx / NHEAD;
    float dt = expf(log_dt[lh]);
    float ar = A_re[idx], ai = A_im[idx];
    float e = expf(dt*ar);
    float sn, cs; sincosf(dt*ai, &sn, &cs);
    float lr = e*cs, li = e*sn;
    float nr = lr - 1.0f, ni = li;
    float inv = 1.0f/(ar*ar + ai*ai);
    float dr = (nr*ar + ni*ai)*inv;
    float di = (ni*ar - nr*ai)*inv;
    float br = B_re[idx], bi = B_im[idx];
    float dbr = br*dr - bi*di;
    float dbi = br*di + bi*dr;
    float cr = C_re[idx], ci = C_im[idx];
    g_co_re[idx] = 2.0f*(cr*dbr - ci*dbi);
    g_co_im[idx] = 2.0f*(cr*dbi + ci*dbr);
    g_lam_re[idx] = lr;
    g_lam_im[idx] = li;
}

// ---------------- weight transpose + fp16 hi/lo split ---------------------------
__global__ void wconv_k(const float* __restrict__ Wk, const float* __restrict__ W1,
                        const float* __restrict__ Wproj, const float* __restrict__ W2,
                        const float* __restrict__ Wout)
{
    int widx = blockIdx.z;
    int l = widx / 5, t = widx % 5;
    const float* src = (t==0 ? Wk : t==1 ? W1 : t==2 ? Wproj : t==3 ? W2 : Wout)
                       + (size_t)l * HDIM * HDIM;
    __shared__ float tile[32][33];
    int tx = threadIdx.x, ty = threadIdx.y;
    int n0 = blockIdx.x*32, k0 = blockIdx.y*32;
    #pragma unroll
    for (int i = 0; i < 4; ++i)
        tile[ty + 8*i][tx] = src[(size_t)(k0 + ty + 8*i)*HDIM + n0 + tx];
    __syncthreads();
    #pragma unroll
    for (int i = 0; i < 4; ++i) {
        float v = tile[tx][ty + 8*i];
        size_t o = (size_t)widx*HDIM*HDIM + (size_t)(n0 + ty + 8*i)*HDIM + k0 + tx;
        __half h, lo; split_hf(v, h, lo);
        WTh[o] = h; WTl[o] = lo;
    }
}

// ---------------- elementwise fp16 of Wk ----------------------------------------
__global__ void esplit_k(const float* __restrict__ Wk)
{
    int idx = blockIdx.x * blockDim.x + threadIdx.x;
    if (idx >= LYRS*HDIM*HDIM) return;
    Gw[idx] = __float2half(Wk[idx]);
}

// ---------------- fused biases ---------------------------------------------------
__global__ void __launch_bounds__(256)
bfuse_k(const float* __restrict__ bk, const float* __restrict__ b1,
        const float* __restrict__ bout, const float* __restrict__ bproj)
{
    const int l = blockIdx.x;
    const int n = blockIdx.y*8 + (threadIdx.x >> 5);
    const int lane = threadIdx.x & 31;
    const __half* wh = WTh + ((size_t)(l*5+1))*HDIM*HDIM + (size_t)n*HDIM;
    const __half* wl = WTl + ((size_t)(l*5+1))*HDIM*HDIM + (size_t)n*HDIM;
    const float* bb = bk + l*HDIM;
    float acc = 0.0f;
    #pragma unroll
    for (int i = 0; i < 16; ++i) {
        int j = lane + 32*i;
        acc = fmaf(bb[j], __half2float(wh[j]) + __half2float(wl[j]), acc);
    }
    #pragma unroll
    for (int o = 16; o; o >>= 1) acc += __shfl_xor_sync(0xffffffffu, acc, o);
    if (lane == 0) {
        Bk1[l*HDIM + n] = acc + b1[l*HDIM + n];
        Cb [l*HDIM + n] = bout[l*HDIM + n] + bproj[l*HDIM + n];
    }
}

// ---------------- fused LN1 + transpose: [B,L,H] fp32 -> LN -> [B,H,L] fp32 ----
__global__ void __launch_bounds__(256)
ln_tr_k(const float* __restrict__ src, const float* __restrict__ g,
        const float* __restrict__ b, float* __restrict__ dst)
{
    extern __shared__ float tile[];          // [512][33]
    __shared__ float mu_s[32], rs_s[32];
    const int tid = threadIdx.x;
    const int t0  = blockIdx.x * 32;
    const int bb  = blockIdx.y;
    const int wid = tid >> 5, lane = tid & 31;

    const float* sp = src + ((size_t)bb*SEQ + t0)*HDIM;
    const int r = tid >> 3, c8 = tid & 7;
    #pragma unroll
    for (int j = 0; j < 16; ++j) {
        int c4 = c8 + 8*j;
        float4 v = *(const float4*)(sp + (size_t)r*HDIM + c4*4);
        tile[(c4*4+0)*33 + r] = v.x;
        tile[(c4*4+1)*33 + r] = v.y;
        tile[(c4*4+2)*33 + r] = v.z;
        tile[(c4*4+3)*33 + r] = v.w;
    }
    __syncthreads();

    #pragma unroll
    for (int rr = wid*4; rr < wid*4 + 4; ++rr) {
        float s = 0.f, q = 0.f;
        #pragma unroll
        for (int j = 0; j < 16; ++j) {
            float v = tile[(lane + 32*j)*33 + rr];
            s += v; q += v*v;
        }
        #pragma unroll
        for (int o = 16; o; o >>= 1) {
            s += __shfl_xor_sync(0xffffffffu, s, o);
            q += __shfl_xor_sync(0xffffffffu, q, o);
        }
        if (lane == 0) {
            float mu = s * (1.0f/HDIM);
            mu_s[rr] = mu;
            rs_s[rr] = rsqrtf(q*(1.0f/HDIM) - mu*mu + 1e-5f);
        }
    }
    __syncthreads();

    float* dp = dst + (size_t)bb*HDIM*SEQ + t0;
    const int tq = tid & 7;
    #pragma unroll
    for (int j = 0; j < 16; ++j) {
        int h = (tid >> 3) + 32*j;
        float gv = __ldg(g + h), bv = __ldg(b + h);
        float4 o;
        o.x = (tile[h*33 + tq*4+0] - mu_s[tq*4+0])*rs_s[tq*4+0]*gv + bv;
        o.y = (tile[h*33 + tq*4+1] - mu_s[tq*4+1])*rs_s[tq*4+1]*gv + bv;
        o.z = (tile[h*33 + tq*4+2] - mu_s[tq*4+2])*rs_s[tq*4+2]*gv + bv;
        o.w = (tile[h*33 + tq*4+3] - mu_s[tq*4+3])*rs_s[tq*4+3]*gv + bv;
        *(float4*)(dp + (size_t)h*SEQ + tq*4) = o;
    }
}

// ---------------- LayerNorm: fp32 in -> fp16 hi/lo out --------------------------
__global__ void __launch_bounds__(128)
ln_k(const float* __restrict__ src, const float* __restrict__ g,
     const float* __restrict__ b,
     __half* __restrict__ dsth, __half* __restrict__ dstl)
{
    const int m = blockIdx.x, tid = threadIdx.x;
    const float4 v = *(const float4*)(src + (size_t)m*HDIM + tid*4);
    float s = v.x + v.y + v.z + v.w;
    float q = v.x*v.x + v.y*v.y + v.z*v.z + v.w*v.w;
    #pragma unroll
    for (int o = 16; o; o >>= 1) {
        s += __shfl_xor_sync(0xffffffffu, s, o);
        q += __shfl_xor_sync(0xffffffffu, q, o);
    }
    __shared__ float ss[4], qq[4], mu_s, rs_s;
    int w = tid >> 5;
    if ((tid & 31) == 0) { ss[w] = s; qq[w] = q; }
    __syncthreads();
    if (tid == 0) {
        float S = ss[0]+ss[1]+ss[2]+ss[3];
        float Q = qq[0]+qq[1]+qq[2]+qq[3];
        float mu = S*(1.0f/HDIM);
        mu_s = mu; rs_s = rsqrtf(Q*(1.0f/HDIM) - mu*mu + 1e-5f);
    }
    __syncthreads();
    const float mu = mu_s, rs = rs_s;
    const float4 gv = *(const float4*)(g + tid*4);
    const float4 bv = *(const float4*)(b + tid*4);
    float4 o;
    o.x = (v.x - mu)*rs*gv.x + bv.x;
    o.y = (v.y - mu)*rs*gv.y + bv.y;
    o.z = (v.z - mu)*rs*gv.z + bv.z;
    o.w = (v.w - mu)*rs*gv.w + bv.w;
    size_t off = (size_t)m*HDIM + tid*4;
    __half h0,h1,h2,h3,l0,l1,l2,l3;
    split_hf(o.x,h0,l0); split_hf(o.y,h1,l1);
    split_hf(o.z,h2,l2); split_hf(o.w,h3,l3);
    __half2 a0 = __halves2half2(h0,h1), a1 = __halves2half2(h2,h3);
    __half2 c0 = __halves2half2(l0,l1), c1 = __halves2half2(l2,l3);
    *(uint2*)(dsth + off) = make_uint2(*(uint32_t*)&a0, *(uint32_t*)&a1);
    *(uint2*)(dstl + off) = make_uint2(*(uint32_t*)&c0, *(uint32_t*)&c1);
}

// ---------------- S4 scan + D-skip + GELU ---------------------------------------
__global__ void __launch_bounds__(128)
scan_k(const float* __restrict__ zt, __half* __restrict__ yh,
       __half* __restrict__ yl, const float* __restrict__ Dvec, int l)
{
    __shared__ float st_s[4][32*36];
    __shared__ float zst[4][32];
    __shared__ float yt[2][32][9];
    const int tid  = threadIdx.x;
    const int wid  = tid >> 5;
    const int lane = tid & 31;
    const int b    = blockIdx.x >> 7;
    const int hg   = blockIdx.x & 127;
    const int h    = hg*4 + wid;
    const int base = l*HDIM*NHEAD + h*NHEAD + lane;
    const float lr = g_lam_re[base], li = g_lam_im[base];
    const float cr = g_co_re[base],  ci = g_co_im[base];
    const float nci = -ci;
    const float dsk = Dvec[h];
    const float* zp = zt + ((size_t)b*HDIM + h)*SEQ;
    float* st = st_s[wid];
    float* zs = zst[wid];
    const int ot = tid >> 2, oh = tid & 3;
    float sr = 0.0f, si = 0.0f;

    float zv = zp[lane];
    for (int t0 = 0; t0 < SEQ; t0 += 32) {
        float zv_next = (t0 + 32 < SEQ) ? zp[t0 + 32 + lane] : 0.0f;
        zs[lane] = zv;
        __syncwarp();
        #pragma unroll
        for (int tt = 0; tt < 32; ++tt) {
            float zv_t = zs[tt];
            float tmp  = fmaf(-li, si, zv_t);
            float nsi  = fmaf(li, sr, lr*si);
            sr = fmaf(lr, sr, tmp);
            si = nsi;
            st[tt*36 + lane] = fmaf(cr, sr, nci*si);
        }
        __syncwarp();
        float a0 = 0.f, a1 = 0.f, a2 = 0.f, a3 = 0.f;
        const float4* rp = (const float4*)&st[lane*36];
        #pragma unroll
        for (int i = 0; i < 8; ++i) {
            float4 v4 = rp[i];
            a0 += v4.x; a1 += v4.y; a2 += v4.z; a3 += v4.w;
        }
        const int buf = (t0 >> 5) & 1;
        yt[buf][lane][wid] = gelu_f((a0 + a1) + (a2 + a3) + dsk * zv);
        __syncthreads();
        float v = yt[buf][ot][oh];
        __half hh, ll; split_hf(v, hh, ll);
        size_t off = ((size_t)(b*SEQ + t0 + ot))*HDIM + hg*4 + oh;
        yh[off] = hh; yl[off] = ll;
        zv = zv_next;
    }
}

// ---------------- fp16x2 mma.sync GEMM: warp 32x64, 2-stage, occ 2 --------------
template<int EPI, bool WF32, bool WHL>
__global__ void __launch_bounds__(256, 2)
tgemm_k(const __half* __restrict__ ah, const __half* __restrict__ al,
        const __half* __restrict__ wq,
        const __half* __restrict__ ah2, const __half* __restrict__ al2,
        const __half* __restrict__ wq2,
        int nch,
        const float* __restrict__ bias, const float* __restrict__ res,
        float* __restrict__ outf,
        __half* __restrict__ outh, __half* __restrict__ outl)
{
    extern __shared__ __align__(1024) char smem[];
    const uint32_t sb = smem_u32(smem);
    const int tid  = threadIdx.x;
    const int wid  = tid >> 5;
    const int lane = tid & 31;
    const int wm   = wid & 3;          // 4 warps over M (32 rows each)
    const int wn   = wid >> 2;         // 2 warps over N (64 cols each)
    const int n0   = blockIdx.x * BN;
    const int m0   = blockIdx.y * BM;

    if (tid < BN) ((float*)smem)[tid] = bias[n0 + tid];

    const __half* Ah = ah + (size_t)m0 * HDIM;
    const __half* Al = al + (size_t)m0 * HDIM;
    const __half* Wq = wq + (size_t)n0 * HDIM;
    const __half* Ah2 = ah2 ? ah2 + (size_t)m0 * HDIM : nullptr;
    const __half* Al2 = al2 ? al2 + (size_t)m0 * HDIM : nullptr;
    const __half* Wq2 = wq2 ? wq2 + (size_t)n0 * HDIM : nullptr;

    const int ldr = tid >> 3, ldc = tid & 7;
    auto load_chunk = [&](int ch, int st) {
        const uint32_t so = sb + SM_ST + st*STAGE_B;
        int cofs = ch * BK;
        const __half *A_h = Ah, *A_l = Al, *W_q = Wq;
        if (cofs >= HDIM) {
            A_h = Ah2; A_l = Al2; W_q = Wq2;
            cofs -= HDIM;
        }
        #pragma unroll
        for (int t = 0; t < 4; ++t) {
            int r = ldr + t*32;
            uint32_t dst = so + swz(r*128 + ldc*16);
            size_t gsrc = (size_t)r*HDIM + cofs + ldc*8;
            CP16(dst,         A_h + gsrc);
            CP16(dst + 16384, A_l + gsrc);
            CP16(dst + 32768, W_q + gsrc);
        }
        CP_COMMIT();
    };

    float acc[2][8][4];
    #pragma unroll
    for (int i = 0; i < 2; ++i)
        #pragma unroll
        for (int j = 0; j < 8; ++j)
            #pragma unroll
            for (int r = 0; r < 4; ++r) acc[i][j][r] = 0.0f;

    load_chunk(0, 0);

    const int lr16 = lane & 15, lk = lane >> 4;
    for (int ch = 0; ch < nch; ++ch) {
        if (ch + 1 < nch) { load_chunk(ch + 1, (ch + 1) & 1); CP_WAIT(1); }
        else              { CP_WAIT(0); }
        __syncthreads();
        const uint32_t so = sb + SM_ST + (ch & 1)*STAGE_B;
        #pragma unroll
        for (int kk = 0; kk < 4; ++kk) {
            const uint32_t ka = kk*32 + lk*16;
            uint32_t fah[2][4], fal[2][4];
            #pragma unroll
            for (int mi = 0; mi < 2; ++mi) {
                uint32_t ad = so + swz((wm*32 + mi*16 + lr16)*128 + ka);
                LDSM_X4(fah[mi][0], fah[mi][1], fah[mi][2], fah[mi][3], ad);
                LDSM_X4(fal[mi][0], fal[mi][1], fal[mi][2], fal[mi][3], ad + 16384);
            }
            uint32_t fb[4][4];
            #pragma unroll
            for (int p = 0; p < 4; ++p) {
                uint32_t bd = so + 32768 + swz((wn*64 + p*16 + lr16)*128 + ka);
                LDSM_X4(fb[p][0], fb[p][1], fb[p][2], fb[p][3], bd);
            }
            #pragma unroll
            for (int mi = 0; mi < 2; ++mi) {
                #pragma unroll
                for (int nj = 0; nj < 8; ++nj) {
                    const int p = nj >> 1, j = nj & 1;
                    MMA16816(acc[mi][nj], fah[mi][0], fah[mi][1], fah[mi][2], fah[mi][3],
                             fb[p][j], fb[p][j+2]);
                    MMA16816(acc[mi][nj], fal[mi][0], fal[mi][1], fal[mi][2], fal[mi][3],
                             fb[p][j], fb[p][j+2]);
                }
            }
        }
        __syncthreads();
    }

    // ---------------- epilogue ----------------
    const float* bsm = (const float*)smem;
    const int rbase = m0 + wm*32;
    const int clb   = wn*64;
    #pragma unroll
    for (int mi = 0; mi < 2; ++mi) {
        #pragma unroll
        for (int nj = 0; nj < 8; ++nj) {
            const int ca = clb + nj*8 + (lane & 3)*2;
            const float b0 = bsm[ca], b1 = bsm[ca + 1];
            #pragma unroll
            for (int hrow = 0; hrow < 2; ++hrow) {
                const int r = rbase + mi*16 + (lane >> 2) + hrow*8;
                float v0 = acc[mi][nj][hrow*2 + 0] + b0;
                float v1 = acc[mi][nj][hrow*2 + 1] + b1;
                const size_t off = (size_t)r * HDIM + n0 + ca;
                if (EPI == 1) {
                    float2 rr = *(const float2*)(res + off);
                    v0 += rr.x; v1 += rr.y;
                }
                if (EPI == 2) { v0 = gelu_f(v0); v1 = gelu_f(v1); }
                if (WF32) *(float2*)(outf + off) = make_float2(v0, v1);
                if (WHL) {
                    __half h0, l0, h1, l1;
                    split_hf(v0, h0, l0); split_hf(v1, h1, l1);
                    __half2 hh = __halves2half2(h0, h1);
                    __half2 ll = __halves2half2(l0, l1);
                    *(uint32_t*)(outh + off) = *(uint32_t*)&hh;
                    *(uint32_t*)(outl + off) = *(uint32_t*)&ll;
                }
            }
        }
    }
}

// ---------------- orchestration --------------------------------------------------
extern "C" void kernel_launch(void* const* d_in, const int* in_sizes, int n_in,
                              void* d_out, int out_size)
{
    const float* x      = (const float*)d_in[0];
    const float* ln1w   = (const float*)d_in[1];
    const float* ln1b   = (const float*)d_in[2];
    const float* ln2w   = (const float*)d_in[3];
    const float* ln2b   = (const float*)d_in[4];
    const float* log_dt = (const float*)d_in[5];
    const float* A_re   = (const float*)d_in[6];
    const float* A_im   = (const float*)d_in[7];
    const float* B_re   = (const float*)d_in[8];
    const float* B_im   = (const float*)d_in[9];
    const float* C_re   = (const float*)d_in[10];
    const float* C_im   = (const float*)d_in[11];
    const float* Dv     = (const float*)d_in[12];
    const float* Wk     = (const float*)d_in[13];
    const float* bk     = (const float*)d_in[14];
    const float* W1     = (const float*)d_in[15];
    const float* b1     = (const float*)d_in[16];
    const float* W2     = (const float*)d_in[17];
    const float* b2     = (const float*)d_in[18];
    const float* Wout   = (const float*)d_in[19];
    const float* bout   = (const float*)d_in[20];
    const float* Wproj  = (const float*)d_in[21];
    const float* bproj  = (const float*)d_in[22];

    cudaFuncSetAttribute(tgemm_k<0,false,true >, cudaFuncAttributeMaxDynamicSharedMemorySize, GEMM_SMEM);
    cudaFuncSetAttribute(tgemm_k<1,true ,true >, cudaFuncAttributeMaxDynamicSharedMemorySize, GEMM_SMEM);
    cudaFuncSetAttribute(tgemm_k<0,true ,false>, cudaFuncAttributeMaxDynamicSharedMemorySize, GEMM_SMEM);
    cudaFuncSetAttribute(tgemm_k<2,false,true >, cudaFuncAttributeMaxDynamicSharedMemorySize, GEMM_SMEM);
    cudaFuncSetAttribute(ln_tr_k, cudaFuncAttributeMaxDynamicSharedMemorySize, LNTR_SMEM);

    float *fo1, *foutb, *ftmp, *zb, *bk1, *cb;
    __half *p0h, *p0l, *p1h, *p1l, *p2h, *p2l, *wth, *wtl, *gw;
    cudaGetSymbolAddress((void**)&fo1,  Fo1);
    cudaGetSymbolAddress((void**)&foutb,FoutB);
    cudaGetSymbolAddress((void**)&ftmp, Ftmp);
    cudaGetSymbolAddress((void**)&p0h,  P0h);
    cudaGetSymbolAddress((void**)&p0l,  P0l);
    cudaGetSymbolAddress((void**)&p1h,  P1h);
    cudaGetSymbolAddress((void**)&p1l,  P1l);
    cudaGetSymbolAddress((void**)&p2h,  P2h);
    cudaGetSymbolAddress((void**)&p2l,  P2l);
    cudaGetSymbolAddress((void**)&wth,  WTh);
    cudaGetSymbolAddress((void**)&wtl,  WTl);
    cudaGetSymbolAddress((void**)&gw,   Gw);
    cudaGetSymbolAddress((void**)&zb,   Zb);
    cudaGetSymbolAddress((void**)&bk1,  Bk1);
    cudaGetSymbolAddress((void**)&cb,   Cb);

    prec_k<<<(LYRS*HDIM*NHEAD + 255)/256, 256>>>(log_dt, A_re, A_im, B_re, B_im, C_re, C_im);
    wconv_k<<<dim3(16,16,10), dim3(32,8)>>>(Wk, W1, Wproj, W2, Wout);
    esplit_k<<<(LYRS*HDIM*HDIM + 255)/256, 256>>>(Wk);
    bfuse_k<<<dim3(LYRS,64), 256>>>(bk, b1, bout, bproj);

    const size_t WB = (size_t)HDIM*HDIM;
    // Wk1^T[n][k] = sum_j W1^T[n][j] * Wk[k][j]  -> overwrite slot (l*5+0)
    for (int l = 0; l < LYRS; ++l) {
        tgemm_k<0,false,true><<<dim3(4,4), 256, GEMM_SMEM>>>(
            wth + (l*5+1)*WB, wtl + (l*5+1)*WB,
            gw + l*WB,
            nullptr, nullptr, nullptr, 8,
            zb, nullptr, nullptr,
            wth + (l*5+0)*WB, wtl + (l*5+0)*WB);
    }

    const dim3 gg(HDIM/BN, MROWS/BM);       // (4, 256)
    const float* prev = x;
    for (int l = 0; l < LYRS; ++l) {
        int vo = l * HDIM;
        const __half *wf = wth + (l*5+0)*WB;   // fused Wk@W1 (fp16)
        const __half *wp = wth + (l*5+2)*WB;
        const __half *w2 = wth + (l*5+3)*WB;
        const __half *wo = wth + (l*5+4)*WB;

        // zT = LN1(prev) transposed -> [B,H,L] fp32 (fused)
        ln_tr_k<<<dim3(SEQ/32, BATCH), 256, LNTR_SMEM>>>(prev, ln1w + vo, ln1b + vo, ftmp);
        // y = gelu(ssm(zT) + z*D) -> P0 hi/lo [B,L,H]
        scan_k<<<1024, 128>>>(ftmp, p0h, p0l, Dv + vo, l);
        // o1 = y @ (Wk@W1) + Bk1 + prev -> Fo1 fp32 + P1 hi/lo
        tgemm_k<1,true ,true ><<<gg, 256, GEMM_SMEM>>>(p0h, p0l, wf,
            nullptr, nullptr, nullptr, 8,
            bk1 + vo, prev, fo1, p1h, p1l);
        // z2 = LN2(o1) -> P0 hi/lo
        ln_k<<<MROWS, 128>>>(fo1, ln2w + vo, ln2b + vo, p0h, p0l);
        // h = gelu(z2 @ W2 + b2) -> P2 hi/lo
        tgemm_k<2,false,true ><<<gg, 256, GEMM_SMEM>>>(p0h, p0l, w2,
            nullptr, nullptr, nullptr, 8,
            b2 + vo, nullptr, nullptr, p2h, p2l);
        // out = [h|o1] @ [Wout;Wproj] + (bout+bproj) -> fp32 (merged K=1024)
        float* op = (l == LYRS-1) ? (float*)d_out : foutb;
        tgemm_k<0,true ,false><<<gg, 256, GEMM_SMEM>>>(p2h, p2l, wo,
            p1h, p1l, wp, 16,
            cb + vo, nullptr, op, nullptr, nullptr);
        prev = foutb;
    }
}

// round 17
// speedup vs baseline: 1.8423x; 1.1111x over previous
#include <cuda_runtime.h>
#include <cuda_fp16.h>
#include <math.h>
#include <stdint.h>

#define LYRS   2
#define HDIM   512
#define NHEAD  32
#define BATCH  8
#define SEQ    4096
#define MROWS  (BATCH*SEQ)
#define BLH    (MROWS*HDIM)

#define BM 128
#define BN 128
#define BK 64
#define STAGE_B 49152               /* Ah16K + Al16K + W16K */
#define SM_ST   1024
#define GEMM_SMEM (SM_ST + 2*STAGE_B)   /* 99328 -> 2 CTAs/SM */
#define LNTR_SMEM (512*33*4)            /* 67584 */

// ---------------- scratch ----------------------------------------------------
__device__ float Fo1[BLH], FoutB[BLH], Ftmp[BLH];
__device__ __half P0h[BLH], P0l[BLH], P1h[BLH], P1l[BLH], P2h[BLH], P2l[BLH];
__device__ __half WTh[10*HDIM*HDIM], WTl[10*HDIM*HDIM];
__device__ __half Gw[LYRS*HDIM*HDIM];
__device__ float Bk1[LYRS*HDIM];
__device__ float Cb [LYRS*HDIM];
__device__ float Zb[HDIM];
__device__ float g_lam_re[LYRS*HDIM*NHEAD], g_lam_im[LYRS*HDIM*NHEAD];
__device__ float g_co_re [LYRS*HDIM*NHEAD], g_co_im [LYRS*HDIM*NHEAD];

// ---------------- PTX helpers --------------------------------------------------
__device__ __forceinline__ uint32_t smem_u32(const void* p) {
    uint32_t a;
    asm("{ .reg .u64 t; cvta.to.shared.u64 t, %1; cvt.u32.u64 %0, t; }"
        : "=r"(a) : "l"(p));
    return a;
}
#define CP16(dst, src) \
    asm volatile("cp.async.cg.shared.global [%0], [%1], 16;" \
        :: "r"(dst), "l"(src) : "memory")
#define CP_COMMIT() asm volatile("cp.async.commit_group;" ::: "memory")
#define CP_WAIT(n)  asm volatile("cp.async.wait_group %0;" :: "n"(n) : "memory")

#define LDSM_X4(r0,r1,r2,r3, addr) \
    asm volatile("ldmatrix.sync.aligned.m8n8.x4.shared.b16 {%0,%1,%2,%3}, [%4];" \
        : "=r"(r0),"=r"(r1),"=r"(r2),"=r"(r3) : "r"(addr))

#define MMA16816(d, a0,a1,a2,a3, b0,b1) \
    asm volatile("mma.sync.aligned.m16n8k16.row.col.f32.f16.f16.f32 " \
        "{%0,%1,%2,%3}, {%4,%5,%6,%7}, {%8,%9}, {%0,%1,%2,%3};" \
        : "+f"((d)[0]),"+f"((d)[1]),"+f"((d)[2]),"+f"((d)[3]) \
        : "r"(a0),"r"(a1),"r"(a2),"r"(a3), "r"(b0),"r"(b1))

__device__ __forceinline__ uint32_t swz(uint32_t off) { return off ^ ((off >> 3) & 0x70); }
__device__ __forceinline__ float gelu_f(float x) {
    return 0.5f * x * (1.0f + erff(x * 0.70710678118654752440f));
}
__device__ __forceinline__ void split_hf(float v, __half& h, __half& l) {
    h = __float2half(v);
    l = __float2half(v - __half2float(h));
}

// ---------------- SSM coefficient precompute ----------------------------------
__global__ void prec_k(const float* __restrict__ log_dt,
                       const float* __restrict__ A_re, const float* __restrict__ A_im,
                       const float* __restrict__ B_re, const float* __restrict__ B_im,
                       const float* __restrict__ C_re, const float* __restrict__ C_im)
{
    int idx = blockIdx.x * blockDim.x + threadIdx.x;
    if (idx >= LYRS*HDIM*NHEAD) return;
    int lh = idx / NHEAD;
    float dt = expf(log_dt[lh]);
    float ar = A_re[idx], ai = A_im[idx];
    float e = expf(dt*ar);
    float sn, cs; sincosf(dt*ai, &sn, &cs);
    float lr = e*cs, li = e*sn;
    float nr = lr - 1.0f, ni = li;
    float inv = 1.0f/(ar*ar + ai*ai);
    float dr = (nr*ar + ni*ai)*inv;
    float di = (ni*ar - nr*ai)*inv;
    float br = B_re[idx], bi = B_im[idx];
    float dbr = br*dr - bi*di;
    float dbi = br*di + bi*dr;
    float cr = C_re[idx], ci = C_im[idx];
    g_co_re[idx] = 2.0f*(cr*dbr - ci*dbi);
    g_co_im[idx] = 2.0f*(cr*dbi + ci*dbr);
    g_lam_re[idx] = lr;
    g_lam_im[idx] = li;
}

// ---------------- weight transpose + fp16 hi/lo split ---------------------------
__global__ void wconv_k(const float* __restrict__ Wk, const float* __restrict__ W1,
                        const float* __restrict__ Wproj, const float* __restrict__ W2,
                        const float* __restrict__ Wout)
{
    int widx = blockIdx.z;
    int l = widx / 5, t = widx % 5;
    const float* src = (t==0 ? Wk : t==1 ? W1 : t==2 ? Wproj : t==3 ? W2 : Wout)
                       + (size_t)l * HDIM * HDIM;
    __shared__ float tile[32][33];
    int tx = threadIdx.x, ty = threadIdx.y;
    int n0 = blockIdx.x*32, k0 = blockIdx.y*32;
    #pragma unroll
    for (int i = 0; i < 4; ++i)
        tile[ty + 8*i][tx] = src[(size_t)(k0 + ty + 8*i)*HDIM + n0 + tx];
    __syncthreads();
    #pragma unroll
    for (int i = 0; i < 4; ++i) {
        float v = tile[tx][ty + 8*i];
        size_t o = (size_t)widx*HDIM*HDIM + (size_t)(n0 + ty + 8*i)*HDIM + k0 + tx;
        __half h, lo; split_hf(v, h, lo);
        WTh[o] = h; WTl[o] = lo;
    }
}

// ---------------- elementwise fp16 of Wk ----------------------------------------
__global__ void esplit_k(const float* __restrict__ Wk)
{
    int idx = blockIdx.x * blockDim.x + threadIdx.x;
    if (idx >= LYRS*HDIM*HDIM) return;
    Gw[idx] = __float2half(Wk[idx]);
}

// ---------------- fused biases ---------------------------------------------------
__global__ void __launch_bounds__(256)
bfuse_k(const float* __restrict__ bk, const float* __restrict__ b1,
        const float* __restrict__ bout, const float* __restrict__ bproj)
{
    const int l = blockIdx.x;
    const int n = blockIdx.y*8 + (threadIdx.x >> 5);
    const int lane = threadIdx.x & 31;
    const __half* wh = WTh + ((size_t)(l*5+1))*HDIM*HDIM + (size_t)n*HDIM;
    const __half* wl = WTl + ((size_t)(l*5+1))*HDIM*HDIM + (size_t)n*HDIM;
    const float* bb = bk + l*HDIM;
    float acc = 0.0f;
    #pragma unroll
    for (int i = 0; i < 16; ++i) {
        int j = lane + 32*i;
        acc = fmaf(bb[j], __half2float(wh[j]) + __half2float(wl[j]), acc);
    }
    #pragma unroll
    for (int o = 16; o; o >>= 1) acc += __shfl_xor_sync(0xffffffffu, acc, o);
    if (lane == 0) {
        Bk1[l*HDIM + n] = acc + b1[l*HDIM + n];
        Cb [l*HDIM + n] = bout[l*HDIM + n] + bproj[l*HDIM + n];
    }
}

// ---------------- fused LN1 + transpose: [B,L,H] fp32 -> LN -> [B,H,L] fp32 ----
__global__ void __launch_bounds__(256)
ln_tr_k(const float* __restrict__ src, const float* __restrict__ g,
        const float* __restrict__ b, float* __restrict__ dst)
{
    extern __shared__ float tile[];          // [512][33]
    __shared__ float mu_s[32], rs_s[32];
    const int tid = threadIdx.x;
    const int t0  = blockIdx.x * 32;
    const int bb  = blockIdx.y;
    const int wid = tid >> 5, lane = tid & 31;

    const float* sp = src + ((size_t)bb*SEQ + t0)*HDIM;
    const int r = tid >> 3, c8 = tid & 7;
    #pragma unroll
    for (int j = 0; j < 16; ++j) {
        int c4 = c8 + 8*j;
        float4 v = *(const float4*)(sp + (size_t)r*HDIM + c4*4);
        tile[(c4*4+0)*33 + r] = v.x;
        tile[(c4*4+1)*33 + r] = v.y;
        tile[(c4*4+2)*33 + r] = v.z;
        tile[(c4*4+3)*33 + r] = v.w;
    }
    __syncthreads();

    #pragma unroll
    for (int rr = wid*4; rr < wid*4 + 4; ++rr) {
        float s = 0.f, q = 0.f;
        #pragma unroll
        for (int j = 0; j < 16; ++j) {
            float v = tile[(lane + 32*j)*33 + rr];
            s += v; q += v*v;
        }
        #pragma unroll
        for (int o = 16; o; o >>= 1) {
            s += __shfl_xor_sync(0xffffffffu, s, o);
            q += __shfl_xor_sync(0xffffffffu, q, o);
        }
        if (lane == 0) {
            float mu = s * (1.0f/HDIM);
            mu_s[rr] = mu;
            rs_s[rr] = rsqrtf(q*(1.0f/HDIM) - mu*mu + 1e-5f);
        }
    }
    __syncthreads();

    float* dp = dst + (size_t)bb*HDIM*SEQ + t0;
    const int tq = tid & 7;
    #pragma unroll
    for (int j = 0; j < 16; ++j) {
        int h = (tid >> 3) + 32*j;
        float gv = __ldg(g + h), bv = __ldg(b + h);
        float4 o;
        o.x = (tile[h*33 + tq*4+0] - mu_s[tq*4+0])*rs_s[tq*4+0]*gv + bv;
        o.y = (tile[h*33 + tq*4+1] - mu_s[tq*4+1])*rs_s[tq*4+1]*gv + bv;
        o.z = (tile[h*33 + tq*4+2] - mu_s[tq*4+2])*rs_s[tq*4+2]*gv + bv;
        o.w = (tile[h*33 + tq*4+3] - mu_s[tq*4+3])*rs_s[tq*4+3]*gv + bv;
        *(float4*)(dp + (size_t)h*SEQ + tq*4) = o;
    }
}

// ---------------- LayerNorm: fp32 in -> fp16 hi/lo out --------------------------
__global__ void __launch_bounds__(128)
ln_k(const float* __restrict__ src, const float* __restrict__ g,
     const float* __restrict__ b,
     __half* __restrict__ dsth, __half* __restrict__ dstl)
{
    const int m = blockIdx.x, tid = threadIdx.x;
    const float4 v = *(const float4*)(src + (size_t)m*HDIM + tid*4);
    float s = v.x + v.y + v.z + v.w;
    float q = v.x*v.x + v.y*v.y + v.z*v.z + v.w*v.w;
    #pragma unroll
    for (int o = 16; o; o >>= 1) {
        s += __shfl_xor_sync(0xffffffffu, s, o);
        q += __shfl_xor_sync(0xffffffffu, q, o);
    }
    __shared__ float ss[4], qq[4], mu_s, rs_s;
    int w = tid >> 5;
    if ((tid & 31) == 0) { ss[w] = s; qq[w] = q; }
    __syncthreads();
    if (tid == 0) {
        float S = ss[0]+ss[1]+ss[2]+ss[3];
        float Q = qq[0]+qq[1]+qq[2]+qq[3];
        float mu = S*(1.0f/HDIM);
        mu_s = mu; rs_s = rsqrtf(Q*(1.0f/HDIM) - mu*mu + 1e-5f);
    }
    __syncthreads();
    const float mu = mu_s, rs = rs_s;
    const float4 gv = *(const float4*)(g + tid*4);
    const float4 bv = *(const float4*)(b + tid*4);
    float4 o;
    o.x = (v.x - mu)*rs*gv.x + bv.x;
    o.y = (v.y - mu)*rs*gv.y + bv.y;
    o.z = (v.z - mu)*rs*gv.z + bv.z;
    o.w = (v.w - mu)*rs*gv.w + bv.w;
    size_t off = (size_t)m*HDIM + tid*4;
    __half h0,h1,h2,h3,l0,l1,l2,l3;
    split_hf(o.x,h0,l0); split_hf(o.y,h1,l1);
    split_hf(o.z,h2,l2); split_hf(o.w,h3,l3);
    __half2 a0 = __halves2half2(h0,h1), a1 = __halves2half2(h2,h3);
    __half2 c0 = __halves2half2(l0,l1), c1 = __halves2half2(l2,l3);
    *(uint2*)(dsth + off) = make_uint2(*(uint32_t*)&a0, *(uint32_t*)&a1);
    *(uint2*)(dstl + off) = make_uint2(*(uint32_t*)&c0, *(uint32_t*)&c1);
}

// ---------------- S4 scan + D-skip + GELU ---------------------------------------
__global__ void __launch_bounds__(128)
scan_k(const float* __restrict__ zt, __half* __restrict__ yh,
       __half* __restrict__ yl, const float* __restrict__ Dvec, int l)
{
    __shared__ float st_s[4][32*36];
    __shared__ float zst[4][32];
    __shared__ float yt[2][32][9];
    const int tid  = threadIdx.x;
    const int wid  = tid >> 5;
    const int lane = tid & 31;
    const int b    = blockIdx.x >> 7;
    const int hg   = blockIdx.x & 127;
    const int h    = hg*4 + wid;
    const int base = l*HDIM*NHEAD + h*NHEAD + lane;
    const float lr = g_lam_re[base], li = g_lam_im[base];
    const float cr = g_co_re[base],  ci = g_co_im[base];
    const float nci = -ci;
    const float dsk = Dvec[h];
    const float* zp = zt + ((size_t)b*HDIM + h)*SEQ;
    float* st = st_s[wid];
    float* zs = zst[wid];
    const int ot = tid >> 2, oh = tid & 3;
    float sr = 0.0f, si = 0.0f;

    float zv = zp[lane];
    for (int t0 = 0; t0 < SEQ; t0 += 32) {
        float zv_next = (t0 + 32 < SEQ) ? zp[t0 + 32 + lane] : 0.0f;
        zs[lane] = zv;
        __syncwarp();
        #pragma unroll
        for (int tt = 0; tt < 32; ++tt) {
            float zv_t = zs[tt];
            float tmp  = fmaf(-li, si, zv_t);
            float nsi  = fmaf(li, sr, lr*si);
            sr = fmaf(lr, sr, tmp);
            si = nsi;
            st[tt*36 + lane] = fmaf(cr, sr, nci*si);
        }
        __syncwarp();
        float a0 = 0.f, a1 = 0.f, a2 = 0.f, a3 = 0.f;
        const float4* rp = (const float4*)&st[lane*36];
        #pragma unroll
        for (int i = 0; i < 8; ++i) {
            float4 v4 = rp[i];
            a0 += v4.x; a1 += v4.y; a2 += v4.z; a3 += v4.w;
        }
        const int buf = (t0 >> 5) & 1;
        yt[buf][lane][wid] = gelu_f((a0 + a1) + (a2 + a3) + dsk * zv);
        __syncthreads();
        float v = yt[buf][ot][oh];
        __half hh, ll; split_hf(v, hh, ll);
        size_t off = ((size_t)(b*SEQ + t0 + ot))*HDIM + hg*4 + oh;
        yh[off] = hh; yl[off] = ll;
        zv = zv_next;
    }
}

// ---------------- fp16 mma.sync GEMM: warp 32x64, 2-stage, occ 2 ----------------
// ALO: A has exact hi/lo pair (2 MMA passes); else single-fp16 A (1 pass).
template<int EPI, bool WF32, bool WHL, bool ALO>
__global__ void __launch_bounds__(256, 2)
tgemm_k(const __half* __restrict__ ah, const __half* __restrict__ al,
        const __half* __restrict__ wq,
        const __half* __restrict__ ah2, const __half* __restrict__ al2,
        const __half* __restrict__ wq2,
        int nch,
        const float* __restrict__ bias, const float* __restrict__ res,
        float* __restrict__ outf,
        __half* __restrict__ outh, __half* __restrict__ outl)
{
    extern __shared__ __align__(1024) char smem[];
    const uint32_t sb = smem_u32(smem);
    const int tid  = threadIdx.x;
    const int wid  = tid >> 5;
    const int lane = tid & 31;
    const int wm   = wid & 3;
    const int wn   = wid >> 2;
    const int n0   = blockIdx.x * BN;
    const int m0   = blockIdx.y * BM;

    if (tid < BN) ((float*)smem)[tid] = bias[n0 + tid];

    const __half* Ah = ah + (size_t)m0 * HDIM;
    const __half* Al = ALO ? al + (size_t)m0 * HDIM : nullptr;
    const __half* Wq = wq + (size_t)n0 * HDIM;
    const __half* Ah2 = ah2 ? ah2 + (size_t)m0 * HDIM : nullptr;
    const __half* Al2 = (ALO && al2) ? al2 + (size_t)m0 * HDIM : nullptr;
    const __half* Wq2 = wq2 ? wq2 + (size_t)n0 * HDIM : nullptr;

    const int ldr = tid >> 3, ldc = tid & 7;
    auto load_chunk = [&](int ch, int st) {
        const uint32_t so = sb + SM_ST + st*STAGE_B;
        int cofs = ch * BK;
        const __half *A_h = Ah, *A_l = Al, *W_q = Wq;
        if (cofs >= HDIM) {
            A_h = Ah2; A_l = Al2; W_q = Wq2;
            cofs -= HDIM;
        }
        #pragma unroll
        for (int t = 0; t < 4; ++t) {
            int r = ldr + t*32;
            uint32_t dst = so + swz(r*128 + ldc*16);
            size_t gsrc = (size_t)r*HDIM + cofs + ldc*8;
            CP16(dst,         A_h + gsrc);
            if (ALO) CP16(dst + 16384, A_l + gsrc);
            CP16(dst + 32768, W_q + gsrc);
        }
        CP_COMMIT();
    };

    float acc[2][8][4];
    #pragma unroll
    for (int i = 0; i < 2; ++i)
        #pragma unroll
        for (int j = 0; j < 8; ++j)
            #pragma unroll
            for (int r = 0; r < 4; ++r) acc[i][j][r] = 0.0f;

    load_chunk(0, 0);

    const int lr16 = lane & 15, lk = lane >> 4;
    for (int ch = 0; ch < nch; ++ch) {
        if (ch + 1 < nch) { load_chunk(ch + 1, (ch + 1) & 1); CP_WAIT(1); }
        else              { CP_WAIT(0); }
        __syncthreads();
        const uint32_t so = sb + SM_ST + (ch & 1)*STAGE_B;
        #pragma unroll
        for (int kk = 0; kk < 4; ++kk) {
            const uint32_t ka = kk*32 + lk*16;
            uint32_t fah[2][4], fal[2][4];
            #pragma unroll
            for (int mi = 0; mi < 2; ++mi) {
                uint32_t ad = so + swz((wm*32 + mi*16 + lr16)*128 + ka);
                LDSM_X4(fah[mi][0], fah[mi][1], fah[mi][2], fah[mi][3], ad);
                if (ALO) LDSM_X4(fal[mi][0], fal[mi][1], fal[mi][2], fal[mi][3], ad + 16384);
            }
            uint32_t fb[4][4];
            #pragma unroll
            for (int p = 0; p < 4; ++p) {
                uint32_t bd = so + 32768 + swz((wn*64 + p*16 + lr16)*128 + ka);
                LDSM_X4(fb[p][0], fb[p][1], fb[p][2], fb[p][3], bd);
            }
            #pragma unroll
            for (int mi = 0; mi < 2; ++mi) {
                #pragma unroll
                for (int nj = 0; nj < 8; ++nj) {
                    const int p = nj >> 1, j = nj & 1;
                    MMA16816(acc[mi][nj], fah[mi][0], fah[mi][1], fah[mi][2], fah[mi][3],
                             fb[p][j], fb[p][j+2]);
                    if (ALO)
                        MMA16816(acc[mi][nj], fal[mi][0], fal[mi][1], fal[mi][2], fal[mi][3],
                                 fb[p][j], fb[p][j+2]);
                }
            }
        }
        __syncthreads();
    }

    // ---------------- epilogue ----------------
    const float* bsm = (const float*)smem;
    const int rbase = m0 + wm*32;
    const int clb   = wn*64;
    #pragma unroll
    for (int mi = 0; mi < 2; ++mi) {
        #pragma unroll
        for (int nj = 0; nj < 8; ++nj) {
            const int ca = clb + nj*8 + (lane & 3)*2;
            const float b0 = bsm[ca], b1 = bsm[ca + 1];
            #pragma unroll
            for (int hrow = 0; hrow < 2; ++hrow) {
                const int r = rbase + mi*16 + (lane >> 2) + hrow*8;
                float v0 = acc[mi][nj][hrow*2 + 0] + b0;
                float v1 = acc[mi][nj][hrow*2 + 1] + b1;
                const size_t off = (size_t)r * HDIM + n0 + ca;
                if (EPI == 1) {
                    float2 rr = *(const float2*)(res + off);
                    v0 += rr.x; v1 += rr.y;
                }
                if (EPI == 2) { v0 = gelu_f(v0); v1 = gelu_f(v1); }
                if (WF32) *(float2*)(outf + off) = make_float2(v0, v1);
                if (WHL) {
                    __half h0, l0, h1, l1;
                    split_hf(v0, h0, l0); split_hf(v1, h1, l1);
                    __half2 hh = __halves2half2(h0, h1);
                    __half2 ll = __halves2half2(l0, l1);
                    *(uint32_t*)(outh + off) = *(uint32_t*)&hh;
                    *(uint32_t*)(outl + off) = *(uint32_t*)&ll;
                }
            }
        }
    }
}

// ---------------- orchestration --------------------------------------------------
extern "C" void kernel_launch(void* const* d_in, const int* in_sizes, int n_in,
                              void* d_out, int out_size)
{
    const float* x      = (const float*)d_in[0];
    const float* ln1w   = (const float*)d_in[1];
    const float* ln1b   = (const float*)d_in[2];
    const float* ln2w   = (const float*)d_in[3];
    const float* ln2b   = (const float*)d_in[4];
    const float* log_dt = (const float*)d_in[5];
    const float* A_re   = (const float*)d_in[6];
    const float* A_im   = (const float*)d_in[7];
    const float* B_re   = (const float*)d_in[8];
    const float* B_im   = (const float*)d_in[9];
    const float* C_re   = (const float*)d_in[10];
    const float* C_im   = (const float*)d_in[11];
    const float* Dv     = (const float*)d_in[12];
    const float* Wk     = (const float*)d_in[13];
    const float* bk     = (const float*)d_in[14];
    const float* W1     = (const float*)d_in[15];
    const float* b1     = (const float*)d_in[16];
    const float* W2     = (const float*)d_in[17];
    const float* b2     = (const float*)d_in[18];
    const float* Wout   = (const float*)d_in[19];
    const float* bout   = (const float*)d_in[20];
    const float* Wproj  = (const float*)d_in[21];
    const float* bproj  = (const float*)d_in[22];

    cudaFuncSetAttribute(tgemm_k<0,false,true ,true >, cudaFuncAttributeMaxDynamicSharedMemorySize, GEMM_SMEM);
    cudaFuncSetAttribute(tgemm_k<1,true ,true ,true >, cudaFuncAttributeMaxDynamicSharedMemorySize, GEMM_SMEM);
    cudaFuncSetAttribute(tgemm_k<2,false,true ,true >, cudaFuncAttributeMaxDynamicSharedMemorySize, GEMM_SMEM);
    cudaFuncSetAttribute(tgemm_k<0,true ,false,false>, cudaFuncAttributeMaxDynamicSharedMemorySize, GEMM_SMEM);
    cudaFuncSetAttribute(ln_tr_k, cudaFuncAttributeMaxDynamicSharedMemorySize, LNTR_SMEM);

    float *fo1, *foutb, *ftmp, *zb, *bk1, *cb;
    __half *p0h, *p0l, *p1h, *p1l, *p2h, *p2l, *wth, *wtl, *gw;
    cudaGetSymbolAddress((void**)&fo1,  Fo1);
    cudaGetSymbolAddress((void**)&foutb,FoutB);
    cudaGetSymbolAddress((void**)&ftmp, Ftmp);
    cudaGetSymbolAddress((void**)&p0h,  P0h);
    cudaGetSymbolAddress((void**)&p0l,  P0l);
    cudaGetSymbolAddress((void**)&p1h,  P1h);
    cudaGetSymbolAddress((void**)&p1l,  P1l);
    cudaGetSymbolAddress((void**)&p2h,  P2h);
    cudaGetSymbolAddress((void**)&p2l,  P2l);
    cudaGetSymbolAddress((void**)&wth,  WTh);
    cudaGetSymbolAddress((void**)&wtl,  WTl);
    cudaGetSymbolAddress((void**)&gw,   Gw);
    cudaGetSymbolAddress((void**)&zb,   Zb);
    cudaGetSymbolAddress((void**)&bk1,  Bk1);
    cudaGetSymbolAddress((void**)&cb,   Cb);

    prec_k<<<(LYRS*HDIM*NHEAD + 255)/256, 256>>>(log_dt, A_re, A_im, B_re, B_im, C_re, C_im);
    wconv_k<<<dim3(16,16,10), dim3(32,8)>>>(Wk, W1, Wproj, W2, Wout);
    esplit_k<<<(LYRS*HDIM*HDIM + 255)/256, 256>>>(Wk);
    bfuse_k<<<dim3(LYRS,64), 256>>>(bk, b1, bout, bproj);

    const size_t WB = (size_t)HDIM*HDIM;
    // Wk1^T[n][k] = sum_j W1^T[n][j] * Wk[k][j]  -> overwrite slot (l*5+0)
    for (int l = 0; l < LYRS; ++l) {
        tgemm_k<0,false,true,true><<<dim3(4,4), 256, GEMM_SMEM>>>(
            wth + (l*5+1)*WB, wtl + (l*5+1)*WB,
            gw + l*WB,
            nullptr, nullptr, nullptr, 8,
            zb, nullptr, nullptr,
            wth + (l*5+0)*WB, wtl + (l*5+0)*WB);
    }

    const dim3 gg(HDIM/BN, MROWS/BM);       // (4, 256)
    const float* prev = x;
    for (int l = 0; l < LYRS; ++l) {
        int vo = l * HDIM;
        const __half *wf = wth + (l*5+0)*WB;   // fused Wk@W1 (fp16)
        const __half *wp = wth + (l*5+2)*WB;
        const __half *w2 = wth + (l*5+3)*WB;
        const __half *wo = wth + (l*5+4)*WB;

        // zT = LN1(prev) transposed -> [B,H,L] fp32 (fused)
        ln_tr_k<<<dim3(SEQ/32, BATCH), 256, LNTR_SMEM>>>(prev, ln1w + vo, ln1b + vo, ftmp);
        // y = gelu(ssm(zT) + z*D) -> P0 hi/lo [B,L,H]
        scan_k<<<1024, 128>>>(ftmp, p0h, p0l, Dv + vo, l);
        // o1 = y @ (Wk@W1) + Bk1 + prev -> Fo1 fp32 + P1 hi/lo   (exact A)
        tgemm_k<1,true ,true ,true ><<<gg, 256, GEMM_SMEM>>>(p0h, p0l, wf,
            nullptr, nullptr, nullptr, 8,
            bk1 + vo, prev, fo1, p1h, p1l);
        // z2 = LN2(o1) -> P0 hi/lo
        ln_k<<<MROWS, 128>>>(fo1, ln2w + vo, ln2b + vo, p0h, p0l);
        // h = gelu(z2 @ W2 + b2) -> P2 hi/lo                      (exact A)
        tgemm_k<2,false,true ,true ><<<gg, 256, GEMM_SMEM>>>(p0h, p0l, w2,
            nullptr, nullptr, nullptr, 8,
            b2 + vo, nullptr, nullptr, p2h, p2l);
        // out = [h|o1] @ [Wout;Wproj] + Cb -> fp32  (K=1024, single-fp16 A)
        float* op = (l == LYRS-1) ? (float*)d_out : foutb;
        tgemm_k<0,true ,false,false><<<gg, 256, GEMM_SMEM>>>(p2h, nullptr, wo,
            p1h, nullptr, wp, 16,
            cb + vo, nullptr, op, nullptr, nullptr);
        prev = foutb;
    }
}